// round 2
// baseline (speedup 1.0000x reference)
#include <cuda_runtime.h>
#include <math.h>

#define BSZ 2
#define TT 1024
#define DM 1024
#define DI 2048
#define DS 128
#define NH 32
#define HDS 64
#define NHA 16
#define HDA 64
#define FFND 4096
#define ZXB 4384
#define XBCD 2304
#define QKVD 1152
#define BT (BSZ*TT)

// ---------------- scratch (device globals; no allocations allowed) ----------------
__device__ float g_h[BT*DM];        // rmsnorm outputs (reused 3x)
__device__ float g_zxb[BT*ZXB];
__device__ float g_xBC[BT*XBCD];
__device__ float g_dt[BT*NH];
__device__ float g_dA[BT*NH];
__device__ float g_yp[2*BT*DI];     // scan partials (n-split in 2)
__device__ float g_y2[BT*DI];
__device__ float g_x2[BT*DM];
__device__ float g_qkv[BT*QKVD];
__device__ float g_qc[BT*DM];
__device__ float g_kc[BT*HDA];
__device__ float g_vc[BT*HDA];
__device__ float g_att[BT*DM];
__device__ float g_x3[BT*DM];
__device__ float g_xk[BT*DM];
__device__ float g_xr[BT*DM];
__device__ float g_kf[BT*FFND];
__device__ float g_kv[BT*DM];

// ---------------- helpers ----------------
__device__ __forceinline__ float block_sum(float v) {
    __shared__ float red[32];
    int lane = threadIdx.x & 31, w = threadIdx.x >> 5;
    #pragma unroll
    for (int o = 16; o; o >>= 1) v += __shfl_xor_sync(0xffffffffu, v, o);
    if (lane == 0) red[w] = v;
    __syncthreads();
    int nw = blockDim.x >> 5;
    float r = (threadIdx.x < nw) ? red[threadIdx.x] : 0.f;
    if (w == 0) {
        #pragma unroll
        for (int o = 16; o; o >>= 1) r += __shfl_xor_sync(0xffffffffu, r, o);
        if (lane == 0) red[0] = r;
    }
    __syncthreads();
    return red[0];
}

// ---------------- rmsnorm (no weight) ----------------
__global__ void rmsnorm_k(const float* __restrict__ x, float* __restrict__ o, float eps) {
    int row = blockIdx.x;
    const float* xr = x + (size_t)row * DM;
    float ss = 0.f;
    for (int c = threadIdx.x; c < DM; c += blockDim.x) { float v = xr[c]; ss = fmaf(v, v, ss); }
    ss = block_sum(ss);
    float sc = rsqrtf(ss / (float)DM + eps);
    float* orow = o + (size_t)row * DM;
    for (int c = threadIdx.x; c < DM; c += blockDim.x) orow[c] = xr[c] * sc;
}

// ---------------- generic fp32 GEMM: C[M,N] = A[M,K] @ B[K,N] (+epilogue) -------
// BM=BN=128, BK=8, 256 threads, 8x8 microtile (split 4+4 halves for conflict-free frags)
__global__ void gemm_k(const float* __restrict__ A, const float* __restrict__ Bw,
                       float* __restrict__ C, int M, int N, int K,
                       const float* __restrict__ res, const float* __restrict__ mul, int epi)
{
    __shared__ float As[8][128];
    __shared__ float Bs[8][128];
    int tid = threadIdx.x;
    int m0 = blockIdx.y * 128, n0 = blockIdx.x * 128;
    int ty = tid >> 4, tx = tid & 15;

    float acc[8][8];
    #pragma unroll
    for (int i = 0; i < 8; i++)
        #pragma unroll
        for (int j = 0; j < 8; j++) acc[i][j] = 0.f;

    int arow = tid >> 1;          // 0..127
    int ak   = (tid & 1) * 4;     // 0 or 4
    int brow = tid >> 5;          // 0..7
    int bcol = (tid & 31) * 4;    // 0..124
    const float* Aptr = A + (size_t)(m0 + arow) * K + ak;
    bool bpred = (n0 + bcol) < N;
    const float* Bptr = Bw + (size_t)brow * N + (n0 + bcol);

    for (int k0 = 0; k0 < K; k0 += 8) {
        float4 av = *(const float4*)(Aptr + k0);
        As[ak + 0][arow] = av.x; As[ak + 1][arow] = av.y;
        As[ak + 2][arow] = av.z; As[ak + 3][arow] = av.w;
        float4 bv = make_float4(0.f, 0.f, 0.f, 0.f);
        if (bpred) bv = *(const float4*)(Bptr + (size_t)k0 * N);
        *(float4*)&Bs[brow][bcol] = bv;
        __syncthreads();
        #pragma unroll
        for (int kk = 0; kk < 8; kk++) {
            float a[8], b[8];
            float4 t0 = *(const float4*)&As[kk][ty * 4];
            float4 t1 = *(const float4*)&As[kk][64 + ty * 4];
            a[0]=t0.x; a[1]=t0.y; a[2]=t0.z; a[3]=t0.w;
            a[4]=t1.x; a[5]=t1.y; a[6]=t1.z; a[7]=t1.w;
            float4 u0 = *(const float4*)&Bs[kk][tx * 4];
            float4 u1 = *(const float4*)&Bs[kk][64 + tx * 4];
            b[0]=u0.x; b[1]=u0.y; b[2]=u0.z; b[3]=u0.w;
            b[4]=u1.x; b[5]=u1.y; b[6]=u1.z; b[7]=u1.w;
            #pragma unroll
            for (int i = 0; i < 8; i++)
                #pragma unroll
                for (int j = 0; j < 8; j++)
                    acc[i][j] = fmaf(a[i], b[j], acc[i][j]);
        }
        __syncthreads();
    }

    #pragma unroll
    for (int i = 0; i < 8; i++) {
        int ri = m0 + ((i < 4) ? (ty * 4 + i) : (64 + ty * 4 + i - 4));
        #pragma unroll
        for (int j = 0; j < 8; j++) {
            int ci = n0 + ((j < 4) ? (tx * 4 + j) : (64 + tx * 4 + j - 4));
            if (ci < N) {
                size_t idx = (size_t)ri * N + ci;
                float v = acc[i][j];
                if (epi == 1)      v += res[idx];
                else if (epi == 2) { v = fmaxf(v, 0.f); v = v * v; }
                else if (epi == 3) v = res[idx] + mul[idx] * (1.f / (1.f + expf(-v)));
                C[idx] = v;
            }
        }
    }
}

// ---------------- xBC causal depthwise conv (K=4) + silu ----------------
__global__ void conv_silu_k(const float* __restrict__ cw, const float* __restrict__ cb) {
    int bt = blockIdx.x; int b = bt >> 10, t = bt & 1023;
    for (int c = threadIdx.x; c < XBCD; c += blockDim.x) {
        float acc = cb[c];
        #pragma unroll
        for (int k = 0; k < 4; k++) {
            int tt = t + k - 3;
            if (tt >= 0) acc = fmaf(cw[c * 4 + k], g_zxb[(size_t)(b * TT + tt) * ZXB + DI + c], acc);
        }
        acc = acc / (1.f + expf(-acc));
        g_xBC[(size_t)bt * XBCD + c] = acc;
    }
}

// ---------------- dt = softplus(raw + bias), dA = exp(dt * A) ----------------
__global__ void dt_k(const float* __restrict__ dt_bias, const float* __restrict__ A_log) {
    int i = blockIdx.x * blockDim.x + threadIdx.x;
    if (i >= BT * NH) return;
    int h = i & 31;
    float v = g_zxb[(size_t)(i >> 5) * ZXB + 4352 + h] + dt_bias[h];
    float sp = (v > 20.f) ? v : log1pf(expf(v));
    g_dt[i] = sp;
    g_dA[i] = expf(sp * (-expf(A_log[h])));
}

// ---------------- SSM scan: 128 blocks = (b,h,n-split), 512 threads ----------------
__global__ void scan_k() {
    int bid = blockIdx.x;
    int ns = bid & 1; int bh = bid >> 1; int b = bh >> 5; int h = bh & 31;
    int tid = threadIdx.x;
    int p = tid >> 3;        // 0..63
    int ng = tid & 7;        // n-subgroup, 8 n each
    __shared__ float sB[16 * 64], sC[16 * 64], sX[16 * 64], sS[16];
    float s[8];
    #pragma unroll
    for (int j = 0; j < 8; j++) s[j] = 0.f;
    int nb = ns * 64;

    for (int ct = 0; ct < TT / 16; ct++) {
        int t0 = ct * 16;
        #pragma unroll
        for (int l = 0; l < 2; l++) {
            int e = tid + l * 512; int tt = e >> 6; int n = e & 63;
            int base = b * TT + t0 + tt;
            sB[e] = g_xBC[(size_t)base * XBCD + DI + nb + n];
            sC[e] = g_xBC[(size_t)base * XBCD + DI + DS + nb + n];
            sX[e] = g_xBC[(size_t)base * XBCD + h * 64 + n] * g_dt[base * NH + h];
        }
        if (tid < 16) sS[tid] = g_dA[(b * TT + t0 + tid) * NH + h];
        __syncthreads();
        for (int tt = 0; tt < 16; tt++) {
            float da = sS[tt];
            float dtx = sX[tt * 64 + p];
            float bb[8], cc[8];
            *(float4*)&bb[0] = *(float4*)&sB[tt * 64 + ng * 8];
            *(float4*)&bb[4] = *(float4*)&sB[tt * 64 + ng * 8 + 4];
            *(float4*)&cc[0] = *(float4*)&sC[tt * 64 + ng * 8];
            *(float4*)&cc[4] = *(float4*)&sC[tt * 64 + ng * 8 + 4];
            float acc = 0.f;
            #pragma unroll
            for (int j = 0; j < 8; j++) {
                s[j] = fmaf(s[j], da, dtx * bb[j]);
                acc = fmaf(s[j], cc[j], acc);
            }
            acc += __shfl_xor_sync(0xffffffffu, acc, 1);
            acc += __shfl_xor_sync(0xffffffffu, acc, 2);
            acc += __shfl_xor_sync(0xffffffffu, acc, 4);
            if (ng == 0)
                g_yp[(size_t)ns * (BT * DI) + (size_t)(b * TT + t0 + tt) * DI + h * 64 + p] = acc;
        }
        __syncthreads();
    }
}

// ---------------- gate: y=(scan + x*D)*silu(z), groupnorm(mnorm_w) ----------------
__global__ void gate_k(const float* __restrict__ Dm, const float* __restrict__ mnw) {
    int bt = blockIdx.x;
    float ss = 0.f;
    for (int c = threadIdx.x; c < DI; c += blockDim.x) {
        float v = g_yp[(size_t)bt * DI + c] + g_yp[(size_t)BT * DI + (size_t)bt * DI + c]
                + g_xBC[(size_t)bt * XBCD + c] * Dm[c >> 6];
        float z = g_zxb[(size_t)bt * ZXB + c];
        v *= z / (1.f + expf(-z));
        g_y2[(size_t)bt * DI + c] = v;
        ss = fmaf(v, v, ss);
    }
    ss = block_sum(ss);
    float sc = rsqrtf(ss / (float)DI + 1e-5f);
    for (int c = threadIdx.x; c < DI; c += blockDim.x)
        g_y2[(size_t)bt * DI + c] *= sc * mnw[c];
}

// ---------------- q/k/v causal depthwise conv (K=3) ----------------
__global__ void convqkv_k(const float* __restrict__ qw, const float* __restrict__ qb,
                          const float* __restrict__ kw, const float* __restrict__ kb,
                          const float* __restrict__ vw, const float* __restrict__ vb) {
    int bt = blockIdx.x; int b = bt >> 10, t = bt & 1023;
    for (int c = threadIdx.x; c < QKVD; c += blockDim.x) {
        const float* w; const float* bias; int d;
        if (c < DM)            { d = c & 63;        w = qw; bias = qb; }
        else if (c < DM + 64)  { d = c - DM;        w = kw; bias = kb; }
        else                   { d = c - DM - 64;   w = vw; bias = vb; }
        float acc = bias[d];
        #pragma unroll
        for (int k = 0; k < 3; k++) {
            int tt = t + k - 2;
            if (tt >= 0) acc = fmaf(w[d * 3 + k], g_qkv[(size_t)(b * TT + tt) * QKVD + c], acc);
        }
        if (c < DM)           g_qc[(size_t)bt * DM + c] = acc;
        else if (c < DM + 64) g_kc[(size_t)bt * 64 + d] = acc;
        else                  g_vc[(size_t)bt * 64 + d] = acc;
    }
}

// ---------------- fused causal attention, 64x64 tiles, online softmax ----------------
// grid: b*256 + h*16 + qb ; 256 threads (16x16), 4x4 microtile
__global__ void attn_k() {
    extern __shared__ float sm[];
    float* qs = sm;              // [64 d][64 r] transposed
    float* ks = sm + 4096;       // [64 d][64 c] transposed
    float* vs = sm + 8192;       // [64 c][64 d]
    float* ps = sm + 12288;      // [64 r][65] padded
    int bid = blockIdx.x;
    int qb = bid & 15; int h = (bid >> 4) & 15; int b = bid >> 8;
    int tid = threadIdx.x; int ty = tid >> 4, tx = tid & 15;

    // load q tile transposed
    {
        int r = tid >> 2; int d0 = (tid & 3) * 16;
        const float* qp = &g_qc[(size_t)(b * TT + qb * 64 + r) * DM + h * 64 + d0];
        #pragma unroll
        for (int q4 = 0; q4 < 4; q4++) {
            float4 v = *(const float4*)(qp + q4 * 4);
            int d = d0 + q4 * 4;
            qs[(d + 0) * 64 + r] = v.x; qs[(d + 1) * 64 + r] = v.y;
            qs[(d + 2) * 64 + r] = v.z; qs[(d + 3) * 64 + r] = v.w;
        }
    }
    float mrow[4], lrow[4], o[4][4];
    #pragma unroll
    for (int i = 0; i < 4; i++) {
        mrow[i] = -1e30f; lrow[i] = 0.f;
        #pragma unroll
        for (int j = 0; j < 4; j++) o[i][j] = 0.f;
    }

    for (int kb = 0; kb <= qb; kb++) {
        __syncthreads();
        {
            int c = tid >> 2; int d0 = (tid & 3) * 16;
            const float* kp = &g_kc[(size_t)(b * TT + kb * 64 + c) * 64 + d0];
            const float* vp = &g_vc[(size_t)(b * TT + kb * 64 + c) * 64 + d0];
            #pragma unroll
            for (int q4 = 0; q4 < 4; q4++) {
                float4 kv = *(const float4*)(kp + q4 * 4);
                int d = d0 + q4 * 4;
                ks[(d + 0) * 64 + c] = kv.x; ks[(d + 1) * 64 + c] = kv.y;
                ks[(d + 2) * 64 + c] = kv.z; ks[(d + 3) * 64 + c] = kv.w;
                float4 vv = *(const float4*)(vp + q4 * 4);
                *(float4*)&vs[c * 64 + d] = vv;
            }
        }
        __syncthreads();

        float sc[4][4];
        #pragma unroll
        for (int i = 0; i < 4; i++)
            #pragma unroll
            for (int j = 0; j < 4; j++) sc[i][j] = 0.f;
        for (int d = 0; d < 64; d++) {
            float4 a  = *(const float4*)&qs[d * 64 + ty * 4];
            float4 bb = *(const float4*)&ks[d * 64 + tx * 4];
            float ar[4] = {a.x, a.y, a.z, a.w};
            float br[4] = {bb.x, bb.y, bb.z, bb.w};
            #pragma unroll
            for (int i = 0; i < 4; i++)
                #pragma unroll
                for (int j = 0; j < 4; j++)
                    sc[i][j] = fmaf(ar[i], br[j], sc[i][j]);
        }
        // scale + causal mask
        #pragma unroll
        for (int i = 0; i < 4; i++) {
            int rg = qb * 64 + ty * 4 + i;
            #pragma unroll
            for (int j = 0; j < 4; j++) {
                int cg = kb * 64 + tx * 4 + j;
                sc[i][j] *= 0.125f;
                if (cg > rg) sc[i][j] = -1e30f;
            }
        }
        // online softmax per row (16 tx lanes share a row)
        #pragma unroll
        for (int i = 0; i < 4; i++) {
            float mx = fmaxf(fmaxf(sc[i][0], sc[i][1]), fmaxf(sc[i][2], sc[i][3]));
            #pragma unroll
            for (int off = 1; off < 16; off <<= 1)
                mx = fmaxf(mx, __shfl_xor_sync(0xffffffffu, mx, off));
            float mn = fmaxf(mrow[i], mx);
            float alpha = __expf(mrow[i] - mn);
            mrow[i] = mn;
            float rs = 0.f;
            #pragma unroll
            for (int j = 0; j < 4; j++) {
                float pv = __expf(sc[i][j] - mn);
                sc[i][j] = pv; rs += pv;
            }
            #pragma unroll
            for (int off = 1; off < 16; off <<= 1)
                rs += __shfl_xor_sync(0xffffffffu, rs, off);
            lrow[i] = lrow[i] * alpha + rs;
            #pragma unroll
            for (int j = 0; j < 4; j++) o[i][j] *= alpha;
            #pragma unroll
            for (int j = 0; j < 4; j++)
                ps[(ty * 4 + i) * 65 + tx * 4 + j] = sc[i][j];
        }
        __syncthreads();
        // P @ V
        for (int c = 0; c < 64; c++) {
            float4 vv = *(const float4*)&vs[c * 64 + tx * 4];
            float vr[4] = {vv.x, vv.y, vv.z, vv.w};
            #pragma unroll
            for (int i = 0; i < 4; i++) {
                float pv = ps[(ty * 4 + i) * 65 + c];
                #pragma unroll
                for (int j = 0; j < 4; j++)
                    o[i][j] = fmaf(pv, vr[j], o[i][j]);
            }
        }
    }
    #pragma unroll
    for (int i = 0; i < 4; i++) {
        float inv = 1.f / lrow[i];
        int r = qb * 64 + ty * 4 + i;
        #pragma unroll
        for (int j = 0; j < 4; j++)
            g_att[(size_t)(b * TT + r) * DM + h * 64 + tx * 4 + j] = o[i][j] * inv;
    }
}

// ---------------- token shift for channel-mix ----------------
__global__ void shift_k(const float* __restrict__ tmk, const float* __restrict__ tmr) {
    int i = blockIdx.x * blockDim.x + threadIdx.x;
    if (i >= BT * DM) return;
    int c = i & 1023; int t = (i >> 10) & 1023;
    float cur = g_h[i];
    float prev = t ? g_h[i - DM] : 0.f;
    float dd = prev - cur;
    g_xk[i] = fmaf(dd, tmk[c], cur);
    g_xr[i] = fmaf(dd, tmr[c], cur);
}

// ---------------- host launch ----------------
extern "C" void kernel_launch(void* const* d_in, const int* in_sizes, int n_in,
                              void* d_out, int out_size) {
    const float* x       = (const float*)d_in[0];
    const float* W_in    = (const float*)d_in[1];
    const float* conv_w  = (const float*)d_in[2];
    const float* conv_b  = (const float*)d_in[3];
    const float* A_log   = (const float*)d_in[4];
    const float* Dm      = (const float*)d_in[5];
    const float* dt_bias = (const float*)d_in[6];
    const float* mnorm_w = (const float*)d_in[7];
    const float* W_out   = (const float*)d_in[8];
    const float* W_qkv   = (const float*)d_in[9];
    const float* W_cproj = (const float*)d_in[10];
    const float* qconv_w = (const float*)d_in[11];
    const float* qconv_b = (const float*)d_in[12];
    const float* kconv_w = (const float*)d_in[13];
    const float* kconv_b = (const float*)d_in[14];
    const float* vconv_w = (const float*)d_in[15];
    const float* vconv_b = (const float*)d_in[16];
    const float* tmk     = (const float*)d_in[17];
    const float* tmr     = (const float*)d_in[18];
    const float* W_key   = (const float*)d_in[19];
    const float* W_rec   = (const float*)d_in[20];
    const float* W_val   = (const float*)d_in[21];
    float* out = (float*)d_out;

    float *p_h, *p_zxb, *p_y2, *p_x2, *p_qkv, *p_att, *p_x3, *p_xk, *p_xr, *p_kf, *p_kv;
    cudaGetSymbolAddress((void**)&p_h, g_h);
    cudaGetSymbolAddress((void**)&p_zxb, g_zxb);
    cudaGetSymbolAddress((void**)&p_y2, g_y2);
    cudaGetSymbolAddress((void**)&p_x2, g_x2);
    cudaGetSymbolAddress((void**)&p_qkv, g_qkv);
    cudaGetSymbolAddress((void**)&p_att, g_att);
    cudaGetSymbolAddress((void**)&p_x3, g_x3);
    cudaGetSymbolAddress((void**)&p_xk, g_xk);
    cudaGetSymbolAddress((void**)&p_xr, g_xr);
    cudaGetSymbolAddress((void**)&p_kf, g_kf);
    cudaGetSymbolAddress((void**)&p_kv, g_kv);

    cudaFuncSetAttribute(attn_k, cudaFuncAttributeMaxDynamicSharedMemorySize, 65792);

    // ---- Mamba2-style block ----
    rmsnorm_k<<<BT, 256>>>(x, p_h, 1e-6f);
    gemm_k<<<dim3((ZXB + 127) / 128, BT / 128), 256>>>(p_h, W_in, p_zxb, BT, ZXB, DM, nullptr, nullptr, 0);
    conv_silu_k<<<BT, 256>>>(conv_w, conv_b);
    dt_k<<<(BT * NH + 255) / 256, 256>>>(dt_bias, A_log);
    scan_k<<<128, 512>>>();
    gate_k<<<BT, 256>>>(Dm, mnorm_w);
    gemm_k<<<dim3(DM / 128, BT / 128), 256>>>(p_y2, W_out, p_x2, BT, DM, DI, x, nullptr, 1);

    // ---- attention block ----
    rmsnorm_k<<<BT, 256>>>(p_x2, p_h, 1e-6f);
    gemm_k<<<dim3(QKVD / 128, BT / 128), 256>>>(p_h, W_qkv, p_qkv, BT, QKVD, DM, nullptr, nullptr, 0);
    convqkv_k<<<BT, 256>>>(qconv_w, qconv_b, kconv_w, kconv_b, vconv_w, vconv_b);
    attn_k<<<BSZ * NHA * (TT / 64), 256, 65792>>>();
    gemm_k<<<dim3(DM / 128, BT / 128), 256>>>(p_att, W_cproj, p_x3, BT, DM, DM, p_x2, nullptr, 1);

    // ---- channel mix ----
    rmsnorm_k<<<BT, 256>>>(p_x3, p_h, 1e-6f);
    shift_k<<<(BT * DM + 255) / 256, 256>>>(tmk, tmr);
    gemm_k<<<dim3(FFND / 128, BT / 128), 256>>>(p_xk, W_key, p_kf, BT, FFND, DM, nullptr, nullptr, 2);
    gemm_k<<<dim3(DM / 128, BT / 128), 256>>>(p_kf, W_val, p_kv, BT, DM, FFND, nullptr, nullptr, 0);
    gemm_k<<<dim3(DM / 128, BT / 128), 256>>>(p_xr, W_rec, out, BT, DM, DM, p_x3, p_kv, 3);
}

// round 6
// speedup vs baseline: 2.4059x; 2.4059x over previous
#include <cuda_runtime.h>
#include <math.h>
#include <stdint.h>

#define BSZ 2
#define TT 1024
#define DM 1024
#define DI 2048
#define DS 128
#define NH 32
#define HDS 64
#define NHA 16
#define HDA 64
#define FFND 4096
#define ZXB 4384
#define XBCD 2304
#define QKVD 1152
#define BT (BSZ*TT)

// ---------------- scratch (device globals; no allocations allowed) ----------------
__device__ float g_h[BT*DM];
__device__ float g_zxb[BT*ZXB];
__device__ float g_xBC[BT*XBCD];
__device__ float g_dt[BT*NH];
__device__ float g_dA[BT*NH];
__device__ float g_yp[2*BT*DI];
__device__ float g_y2[BT*DI];
__device__ float g_x2[BT*DM];
__device__ float g_qkv[BT*QKVD];
__device__ float g_qc[BT*DM];
__device__ float g_kc[BT*HDA];
__device__ float g_vc[BT*HDA];
__device__ float g_att[BT*DM];
__device__ float g_x3[BT*DM];
__device__ float g_xk[BT*DM];
__device__ float g_xr[BT*DM];
__device__ float g_kf[BT*FFND];
__device__ float g_kv[BT*DM];

// ---------------- helpers ----------------
__device__ __forceinline__ float block_sum(float v) {
    __shared__ float red[32];
    int lane = threadIdx.x & 31, w = threadIdx.x >> 5;
    #pragma unroll
    for (int o = 16; o; o >>= 1) v += __shfl_xor_sync(0xffffffffu, v, o);
    if (lane == 0) red[w] = v;
    __syncthreads();
    int nw = blockDim.x >> 5;
    float r = (threadIdx.x < nw) ? red[threadIdx.x] : 0.f;
    if (w == 0) {
        #pragma unroll
        for (int o = 16; o; o >>= 1) r += __shfl_xor_sync(0xffffffffu, r, o);
        if (lane == 0) red[0] = r;
    }
    __syncthreads();
    return red[0];
}

__global__ void rmsnorm_k(const float* __restrict__ x, float* __restrict__ o, float eps) {
    int row = blockIdx.x;
    const float* xr = x + (size_t)row * DM;
    float ss = 0.f;
    for (int c = threadIdx.x; c < DM; c += blockDim.x) { float v = xr[c]; ss = fmaf(v, v, ss); }
    ss = block_sum(ss);
    float sc = rsqrtf(ss / (float)DM + eps);
    float* orow = o + (size_t)row * DM;
    for (int c = threadIdx.x; c < DM; c += blockDim.x) orow[c] = xr[c] * sc;
}

// ================= tf32 mma.sync GEMM =================
// C[M,N] = A[M,K] @ B[K,N] (+fused epilogue). 128x128x16 tiles, cp.async double buffer.
__device__ __forceinline__ uint32_t f2tf32(float x) {
    uint32_t r; asm("cvt.rna.tf32.f32 %0, %1;" : "=r"(r) : "f"(x)); return r;
}
#define CP_ASYNC16(dst, src, sz) \
    asm volatile("cp.async.cg.shared.global [%0], [%1], 16, %2;" :: "r"(dst), "l"(src), "r"(sz) : "memory")
#define CP_COMMIT() asm volatile("cp.async.commit_group;" ::: "memory")
#define CP_WAIT0()  asm volatile("cp.async.wait_group 0;" ::: "memory")
#define CP_WAIT1()  asm volatile("cp.async.wait_group 1;" ::: "memory")
#define MMA_TF32(d, a, b) \
    asm volatile("mma.sync.aligned.m16n8k8.row.col.f32.tf32.tf32.f32 " \
        "{%0,%1,%2,%3}, {%4,%5,%6,%7}, {%8,%9}, {%0,%1,%2,%3};" \
        : "+f"((d)[0]), "+f"((d)[1]), "+f"((d)[2]), "+f"((d)[3]) \
        : "r"((a)[0]), "r"((a)[1]), "r"((a)[2]), "r"((a)[3]), "r"((b)[0]), "r"((b)[1]))

__global__ void __launch_bounds__(256) gemm_tc(const float* __restrict__ A, const float* __restrict__ B,
                                               float* __restrict__ C, int M, int N, int K,
                                               const float* __restrict__ res, const float* __restrict__ mul, int epi)
{
    __shared__ float As[2][128][20];   // row stride 20 floats (16B-aligned, conflict-free frags)
    __shared__ float Bs[2][16][136];   // row stride 136 floats (16B-aligned, conflict-free frags)
    int tid = threadIdx.x;
    int m0 = blockIdx.y * 128, n0 = blockIdx.x * 128;
    int w = tid >> 5, lane = tid & 31;
    int wm = (w >> 2) * 64;           // warp row offset (0/64)
    int wn = (w & 3) * 32;            // warp col offset (0/32/64/96)

    float acc[4][4][4];
    #pragma unroll
    for (int mi = 0; mi < 4; mi++)
        #pragma unroll
        for (int ni = 0; ni < 4; ni++)
            #pragma unroll
            for (int e = 0; e < 4; e++) acc[mi][ni][e] = 0.f;

    const int NC = K >> 4;

    // async tile fill: A 128x16, B 16x128
    auto fill = [&](int buf, int k0) {
        #pragma unroll
        for (int i = 0; i < 2; i++) {
            int task = tid + i * 256;
            int r = task >> 2, q = (task & 3) * 4;
            const float* src = A + (size_t)(m0 + r) * K + k0 + q;
            uint32_t dst = (uint32_t)__cvta_generic_to_shared(&As[buf][r][q]);
            CP_ASYNC16(dst, src, 16);
        }
        #pragma unroll
        for (int i = 0; i < 2; i++) {
            int task = tid + i * 256;
            int kk = task >> 5, c4 = (task & 31) * 4;
            int ok = (n0 + c4) < N;
            const float* src = B + (size_t)(k0 + kk) * N + (ok ? (n0 + c4) : 0);
            uint32_t dst = (uint32_t)__cvta_generic_to_shared(&Bs[buf][kk][c4]);
            CP_ASYNC16(dst, src, ok ? 16 : 0);
        }
    };

    fill(0, 0);
    CP_COMMIT();

    int arow = lane >> 2, acol = lane & 3;
    int bk = lane & 3, bn = lane >> 2;

    for (int ct = 0; ct < NC; ct++) {
        int buf = ct & 1;
        if (ct + 1 < NC) { fill(buf ^ 1, (ct + 1) * 16); CP_COMMIT(); CP_WAIT1(); }
        else             { CP_WAIT0(); }
        __syncthreads();

        const float (*as)[20]  = As[buf];
        const float (*bs)[136] = Bs[buf];
        #pragma unroll
        for (int ks = 0; ks < 2; ks++) {
            int kb = ks * 8;
            uint32_t af[4][4];
            #pragma unroll
            for (int mi = 0; mi < 4; mi++) {
                int r = wm + mi * 16 + arow;
                af[mi][0] = f2tf32(as[r][kb + acol]);
                af[mi][1] = f2tf32(as[r + 8][kb + acol]);
                af[mi][2] = f2tf32(as[r][kb + acol + 4]);
                af[mi][3] = f2tf32(as[r + 8][kb + acol + 4]);
            }
            uint32_t bf[4][2];
            #pragma unroll
            for (int ni = 0; ni < 4; ni++) {
                int c = wn + ni * 8 + bn;
                bf[ni][0] = f2tf32(bs[kb + bk][c]);
                bf[ni][1] = f2tf32(bs[kb + bk + 4][c]);
            }
            #pragma unroll
            for (int mi = 0; mi < 4; mi++)
                #pragma unroll
                for (int ni = 0; ni < 4; ni++)
                    MMA_TF32(acc[mi][ni], af[mi], bf[ni]);
        }
        __syncthreads();
    }

    // epilogue
    #pragma unroll
    for (int mi = 0; mi < 4; mi++) {
        int r0 = m0 + wm + mi * 16 + (lane >> 2);
        #pragma unroll
        for (int ni = 0; ni < 4; ni++) {
            int c = n0 + wn + ni * 8 + (lane & 3) * 2;
            if (c < N) {
                #pragma unroll
                for (int half = 0; half < 2; half++) {
                    int r = r0 + half * 8;
                    size_t idx = (size_t)r * N + c;
                    float v0 = acc[mi][ni][half * 2 + 0];
                    float v1 = acc[mi][ni][half * 2 + 1];
                    if (epi == 1) {
                        v0 += res[idx]; v1 += res[idx + 1];
                    } else if (epi == 2) {
                        v0 = fmaxf(v0, 0.f); v0 *= v0;
                        v1 = fmaxf(v1, 0.f); v1 *= v1;
                    } else if (epi == 3) {
                        v0 = res[idx]     + mul[idx]     / (1.f + expf(-v0));
                        v1 = res[idx + 1] + mul[idx + 1] / (1.f + expf(-v1));
                    }
                    C[idx] = v0; C[idx + 1] = v1;
                }
            }
        }
    }
}

// ---------------- xBC causal depthwise conv (K=4) + silu ----------------
__global__ void conv_silu_k(const float* __restrict__ cw, const float* __restrict__ cb) {
    int bt = blockIdx.x; int b = bt >> 10, t = bt & 1023;
    for (int c = threadIdx.x; c < XBCD; c += blockDim.x) {
        float acc = cb[c];
        #pragma unroll
        for (int k = 0; k < 4; k++) {
            int tt = t + k - 3;
            if (tt >= 0) acc = fmaf(cw[c * 4 + k], g_zxb[(size_t)(b * TT + tt) * ZXB + DI + c], acc);
        }
        acc = acc / (1.f + expf(-acc));
        g_xBC[(size_t)bt * XBCD + c] = acc;
    }
}

__global__ void dt_k(const float* __restrict__ dt_bias, const float* __restrict__ A_log) {
    int i = blockIdx.x * blockDim.x + threadIdx.x;
    if (i >= BT * NH) return;
    int h = i & 31;
    float v = g_zxb[(size_t)(i >> 5) * ZXB + 4352 + h] + dt_bias[h];
    float sp = (v > 20.f) ? v : log1pf(expf(v));
    g_dt[i] = sp;
    g_dA[i] = expf(sp * (-expf(A_log[h])));
}

// ---------------- SSM scan ----------------
__global__ void scan_k() {
    int bid = blockIdx.x;
    int ns = bid & 1; int bh = bid >> 1; int b = bh >> 5; int h = bh & 31;
    int tid = threadIdx.x;
    int p = tid >> 3;
    int ng = tid & 7;
    __shared__ float sB[16 * 64], sC[16 * 64], sX[16 * 64], sS[16];
    float s[8];
    #pragma unroll
    for (int j = 0; j < 8; j++) s[j] = 0.f;
    int nb = ns * 64;

    for (int ct = 0; ct < TT / 16; ct++) {
        int t0 = ct * 16;
        #pragma unroll
        for (int l = 0; l < 2; l++) {
            int e = tid + l * 512; int tt = e >> 6; int n = e & 63;
            int base = b * TT + t0 + tt;
            sB[e] = g_xBC[(size_t)base * XBCD + DI + nb + n];
            sC[e] = g_xBC[(size_t)base * XBCD + DI + DS + nb + n];
            sX[e] = g_xBC[(size_t)base * XBCD + h * 64 + n] * g_dt[base * NH + h];
        }
        if (tid < 16) sS[tid] = g_dA[(b * TT + t0 + tid) * NH + h];
        __syncthreads();
        for (int tt = 0; tt < 16; tt++) {
            float da = sS[tt];
            float dtx = sX[tt * 64 + p];
            float bb[8], cc[8];
            *(float4*)&bb[0] = *(float4*)&sB[tt * 64 + ng * 8];
            *(float4*)&bb[4] = *(float4*)&sB[tt * 64 + ng * 8 + 4];
            *(float4*)&cc[0] = *(float4*)&sC[tt * 64 + ng * 8];
            *(float4*)&cc[4] = *(float4*)&sC[tt * 64 + ng * 8 + 4];
            float acc = 0.f;
            #pragma unroll
            for (int j = 0; j < 8; j++) {
                s[j] = fmaf(s[j], da, dtx * bb[j]);
                acc = fmaf(s[j], cc[j], acc);
            }
            acc += __shfl_xor_sync(0xffffffffu, acc, 1);
            acc += __shfl_xor_sync(0xffffffffu, acc, 2);
            acc += __shfl_xor_sync(0xffffffffu, acc, 4);
            if (ng == 0)
                g_yp[(size_t)ns * (BT * DI) + (size_t)(b * TT + t0 + tt) * DI + h * 64 + p] = acc;
        }
        __syncthreads();
    }
}

__global__ void gate_k(const float* __restrict__ Dm, const float* __restrict__ mnw) {
    int bt = blockIdx.x;
    float ss = 0.f;
    for (int c = threadIdx.x; c < DI; c += blockDim.x) {
        float v = g_yp[(size_t)bt * DI + c] + g_yp[(size_t)BT * DI + (size_t)bt * DI + c]
                + g_xBC[(size_t)bt * XBCD + c] * Dm[c >> 6];
        float z = g_zxb[(size_t)bt * ZXB + c];
        v *= z / (1.f + expf(-z));
        g_y2[(size_t)bt * DI + c] = v;
        ss = fmaf(v, v, ss);
    }
    ss = block_sum(ss);
    float sc = rsqrtf(ss / (float)DI + 1e-5f);
    for (int c = threadIdx.x; c < DI; c += blockDim.x)
        g_y2[(size_t)bt * DI + c] *= sc * mnw[c];
}

__global__ void convqkv_k(const float* __restrict__ qw, const float* __restrict__ qb,
                          const float* __restrict__ kw, const float* __restrict__ kb,
                          const float* __restrict__ vw, const float* __restrict__ vb) {
    int bt = blockIdx.x; int b = bt >> 10, t = bt & 1023;
    for (int c = threadIdx.x; c < QKVD; c += blockDim.x) {
        const float* w; const float* bias; int d;
        if (c < DM)            { d = c & 63;        w = qw; bias = qb; }
        else if (c < DM + 64)  { d = c - DM;        w = kw; bias = kb; }
        else                   { d = c - DM - 64;   w = vw; bias = vb; }
        float acc = bias[d];
        #pragma unroll
        for (int k = 0; k < 3; k++) {
            int tt = t + k - 2;
            if (tt >= 0) acc = fmaf(w[d * 3 + k], g_qkv[(size_t)(b * TT + tt) * QKVD + c], acc);
        }
        if (c < DM)           g_qc[(size_t)bt * DM + c] = acc;
        else if (c < DM + 64) g_kc[(size_t)bt * 64 + d] = acc;
        else                  g_vc[(size_t)bt * 64 + d] = acc;
    }
}

// ---------------- fused causal attention ----------------
__global__ void attn_k() {
    extern __shared__ float sm[];
    float* qs = sm;
    float* ks = sm + 4096;
    float* vs = sm + 8192;
    float* ps = sm + 12288;
    int bid = blockIdx.x;
    int qb = bid & 15; int h = (bid >> 4) & 15; int b = bid >> 8;
    int tid = threadIdx.x; int ty = tid >> 4, tx = tid & 15;

    {
        int r = tid >> 2; int d0 = (tid & 3) * 16;
        const float* qp = &g_qc[(size_t)(b * TT + qb * 64 + r) * DM + h * 64 + d0];
        #pragma unroll
        for (int q4 = 0; q4 < 4; q4++) {
            float4 v = *(const float4*)(qp + q4 * 4);
            int d = d0 + q4 * 4;
            qs[(d + 0) * 64 + r] = v.x; qs[(d + 1) * 64 + r] = v.y;
            qs[(d + 2) * 64 + r] = v.z; qs[(d + 3) * 64 + r] = v.w;
        }
    }
    float mrow[4], lrow[4], o[4][4];
    #pragma unroll
    for (int i = 0; i < 4; i++) {
        mrow[i] = -1e30f; lrow[i] = 0.f;
        #pragma unroll
        for (int j = 0; j < 4; j++) o[i][j] = 0.f;
    }

    for (int kb = 0; kb <= qb; kb++) {
        __syncthreads();
        {
            int c = tid >> 2; int d0 = (tid & 3) * 16;
            const float* kp = &g_kc[(size_t)(b * TT + kb * 64 + c) * 64 + d0];
            const float* vp = &g_vc[(size_t)(b * TT + kb * 64 + c) * 64 + d0];
            #pragma unroll
            for (int q4 = 0; q4 < 4; q4++) {
                float4 kv = *(const float4*)(kp + q4 * 4);
                int d = d0 + q4 * 4;
                ks[(d + 0) * 64 + c] = kv.x; ks[(d + 1) * 64 + c] = kv.y;
                ks[(d + 2) * 64 + c] = kv.z; ks[(d + 3) * 64 + c] = kv.w;
                float4 vv = *(const float4*)(vp + q4 * 4);
                *(float4*)&vs[c * 64 + d] = vv;
            }
        }
        __syncthreads();

        float sc[4][4];
        #pragma unroll
        for (int i = 0; i < 4; i++)
            #pragma unroll
            for (int j = 0; j < 4; j++) sc[i][j] = 0.f;
        for (int d = 0; d < 64; d++) {
            float4 a  = *(const float4*)&qs[d * 64 + ty * 4];
            float4 bb = *(const float4*)&ks[d * 64 + tx * 4];
            float ar[4] = {a.x, a.y, a.z, a.w};
            float br[4] = {bb.x, bb.y, bb.z, bb.w};
            #pragma unroll
            for (int i = 0; i < 4; i++)
                #pragma unroll
                for (int j = 0; j < 4; j++)
                    sc[i][j] = fmaf(ar[i], br[j], sc[i][j]);
        }
        #pragma unroll
        for (int i = 0; i < 4; i++) {
            int rg = qb * 64 + ty * 4 + i;
            #pragma unroll
            for (int j = 0; j < 4; j++) {
                int cg = kb * 64 + tx * 4 + j;
                sc[i][j] *= 0.125f;
                if (cg > rg) sc[i][j] = -1e30f;
            }
        }
        #pragma unroll
        for (int i = 0; i < 4; i++) {
            float mx = fmaxf(fmaxf(sc[i][0], sc[i][1]), fmaxf(sc[i][2], sc[i][3]));
            #pragma unroll
            for (int off = 1; off < 16; off <<= 1)
                mx = fmaxf(mx, __shfl_xor_sync(0xffffffffu, mx, off));
            float mn = fmaxf(mrow[i], mx);
            float alpha = __expf(mrow[i] - mn);
            mrow[i] = mn;
            float rs = 0.f;
            #pragma unroll
            for (int j = 0; j < 4; j++) {
                float pv = __expf(sc[i][j] - mn);
                sc[i][j] = pv; rs += pv;
            }
            #pragma unroll
            for (int off = 1; off < 16; off <<= 1)
                rs += __shfl_xor_sync(0xffffffffu, rs, off);
            lrow[i] = lrow[i] * alpha + rs;
            #pragma unroll
            for (int j = 0; j < 4; j++) o[i][j] *= alpha;
            #pragma unroll
            for (int j = 0; j < 4; j++)
                ps[(ty * 4 + i) * 65 + tx * 4 + j] = sc[i][j];
        }
        __syncthreads();
        for (int c = 0; c < 64; c++) {
            float4 vv = *(const float4*)&vs[c * 64 + tx * 4];
            float vr[4] = {vv.x, vv.y, vv.z, vv.w};
            #pragma unroll
            for (int i = 0; i < 4; i++) {
                float pv = ps[(ty * 4 + i) * 65 + c];
                #pragma unroll
                for (int j = 0; j < 4; j++)
                    o[i][j] = fmaf(pv, vr[j], o[i][j]);
            }
        }
    }
    #pragma unroll
    for (int i = 0; i < 4; i++) {
        float inv = 1.f / lrow[i];
        int r = qb * 64 + ty * 4 + i;
        #pragma unroll
        for (int j = 0; j < 4; j++)
            g_att[(size_t)(b * TT + r) * DM + h * 64 + tx * 4 + j] = o[i][j] * inv;
    }
}

__global__ void shift_k(const float* __restrict__ tmk, const float* __restrict__ tmr) {
    int i = blockIdx.x * blockDim.x + threadIdx.x;
    if (i >= BT * DM) return;
    int c = i & 1023; int t = (i >> 10) & 1023;
    float cur = g_h[i];
    float prev = t ? g_h[i - DM] : 0.f;
    float dd = prev - cur;
    g_xk[i] = fmaf(dd, tmk[c], cur);
    g_xr[i] = fmaf(dd, tmr[c], cur);
}

// ---------------- host launch ----------------
static void run_gemm(const float* A, const float* W, float* C, int M, int N, int K,
                     const float* res, const float* mul, int epi) {
    gemm_tc<<<dim3((N + 127) / 128, M / 128), 256>>>(A, W, C, M, N, K, res, mul, epi);
}

extern "C" void kernel_launch(void* const* d_in, const int* in_sizes, int n_in,
                              void* d_out, int out_size) {
    const float* x       = (const float*)d_in[0];
    const float* W_in    = (const float*)d_in[1];
    const float* conv_w  = (const float*)d_in[2];
    const float* conv_b  = (const float*)d_in[3];
    const float* A_log   = (const float*)d_in[4];
    const float* Dm      = (const float*)d_in[5];
    const float* dt_bias = (const float*)d_in[6];
    const float* mnorm_w = (const float*)d_in[7];
    const float* W_out   = (const float*)d_in[8];
    const float* W_qkv   = (const float*)d_in[9];
    const float* W_cproj = (const float*)d_in[10];
    const float* qconv_w = (const float*)d_in[11];
    const float* qconv_b = (const float*)d_in[12];
    const float* kconv_w = (const float*)d_in[13];
    const float* kconv_b = (const float*)d_in[14];
    const float* vconv_w = (const float*)d_in[15];
    const float* vconv_b = (const float*)d_in[16];
    const float* tmk     = (const float*)d_in[17];
    const float* tmr     = (const float*)d_in[18];
    const float* W_key   = (const float*)d_in[19];
    const float* W_rec   = (const float*)d_in[20];
    const float* W_val   = (const float*)d_in[21];
    float* out = (float*)d_out;

    float *p_h, *p_zxb, *p_y2, *p_x2, *p_qkv, *p_att, *p_x3, *p_xk, *p_xr, *p_kf, *p_kv;
    cudaGetSymbolAddress((void**)&p_h, g_h);
    cudaGetSymbolAddress((void**)&p_zxb, g_zxb);
    cudaGetSymbolAddress((void**)&p_y2, g_y2);
    cudaGetSymbolAddress((void**)&p_x2, g_x2);
    cudaGetSymbolAddress((void**)&p_qkv, g_qkv);
    cudaGetSymbolAddress((void**)&p_att, g_att);
    cudaGetSymbolAddress((void**)&p_x3, g_x3);
    cudaGetSymbolAddress((void**)&p_xk, g_xk);
    cudaGetSymbolAddress((void**)&p_xr, g_xr);
    cudaGetSymbolAddress((void**)&p_kf, g_kf);
    cudaGetSymbolAddress((void**)&p_kv, g_kv);

    cudaFuncSetAttribute(attn_k, cudaFuncAttributeMaxDynamicSharedMemorySize, 65792);

    // ---- Mamba2-style block ----
    rmsnorm_k<<<BT, 256>>>(x, p_h, 1e-6f);
    run_gemm(p_h, W_in, p_zxb, BT, ZXB, DM, nullptr, nullptr, 0);
    conv_silu_k<<<BT, 256>>>(conv_w, conv_b);
    dt_k<<<(BT * NH + 255) / 256, 256>>>(dt_bias, A_log);
    scan_k<<<128, 512>>>();
    gate_k<<<BT, 256>>>(Dm, mnorm_w);
    run_gemm(p_y2, W_out, p_x2, BT, DM, DI, x, nullptr, 1);

    // ---- attention block ----
    rmsnorm_k<<<BT, 256>>>(p_x2, p_h, 1e-6f);
    run_gemm(p_h, W_qkv, p_qkv, BT, QKVD, DM, nullptr, nullptr, 0);
    convqkv_k<<<BT, 256>>>(qconv_w, qconv_b, kconv_w, kconv_b, vconv_w, vconv_b);
    attn_k<<<BSZ * NHA * (TT / 64), 256, 65792>>>();
    run_gemm(p_att, W_cproj, p_x3, BT, DM, DM, p_x2, nullptr, 1);

    // ---- channel mix ----
    rmsnorm_k<<<BT, 256>>>(p_x3, p_h, 1e-6f);
    shift_k<<<(BT * DM + 255) / 256, 256>>>(tmk, tmr);
    run_gemm(p_xk, W_key, p_kf, BT, FFND, DM, nullptr, nullptr, 2);
    run_gemm(p_kf, W_val, p_kv, BT, DM, FFND, nullptr, nullptr, 0);
    run_gemm(p_xr, W_rec, out, BT, DM, DM, p_x3, p_kv, 3);
}

// round 7
// speedup vs baseline: 2.6590x; 1.1052x over previous
#include <cuda_runtime.h>
#include <math.h>
#include <stdint.h>

#define BSZ 2
#define TT 1024
#define DM 1024
#define DI 2048
#define DS 128
#define NH 32
#define HDS 64
#define NHA 16
#define HDA 64
#define FFND 4096
#define ZXB 4384
#define XBCD 2304
#define QKVD 1152
#define BT (BSZ*TT)

// ---------------- scratch (device globals; no allocations allowed) ----------------
__device__ float g_h[BT*DM];
__device__ float g_zxb[BT*ZXB];
__device__ float g_xBC[BT*XBCD];
__device__ float g_dt[BT*NH];
__device__ float g_dA[BT*NH];
__device__ float g_yp[2*BT*DI];
__device__ float g_y2[BT*DI];
__device__ float g_x2[BT*DM];
__device__ float g_qkv[BT*QKVD];
__device__ float g_qc[BT*DM];
__device__ float g_kc[BT*HDA];
__device__ float g_vc[BT*HDA];
__device__ float g_att[BT*DM];
__device__ float g_x3[BT*DM];
__device__ float g_xk[BT*DM];
__device__ float g_xr[BT*DM];
__device__ float g_kf[BT*FFND];
__device__ float g_kv[BT*DM];

// ---------------- helpers ----------------
__device__ __forceinline__ float block_sum(float v) {
    __shared__ float red[32];
    int lane = threadIdx.x & 31, w = threadIdx.x >> 5;
    #pragma unroll
    for (int o = 16; o; o >>= 1) v += __shfl_xor_sync(0xffffffffu, v, o);
    if (lane == 0) red[w] = v;
    __syncthreads();
    int nw = blockDim.x >> 5;
    float r = (threadIdx.x < nw) ? red[threadIdx.x] : 0.f;
    if (w == 0) {
        #pragma unroll
        for (int o = 16; o; o >>= 1) r += __shfl_xor_sync(0xffffffffu, r, o);
        if (lane == 0) red[0] = r;
    }
    __syncthreads();
    return red[0];
}

__global__ void rmsnorm_k(const float* __restrict__ x, float* __restrict__ o, float eps) {
    int row = blockIdx.x;
    const float* xr = x + (size_t)row * DM;
    float ss = 0.f;
    for (int c = threadIdx.x; c < DM; c += blockDim.x) { float v = xr[c]; ss = fmaf(v, v, ss); }
    ss = block_sum(ss);
    float sc = rsqrtf(ss / (float)DM + eps);
    float* orow = o + (size_t)row * DM;
    for (int c = threadIdx.x; c < DM; c += blockDim.x) orow[c] = xr[c] * sc;
}

// ================= tf32 mma.sync GEMM =================
__device__ __forceinline__ uint32_t f2tf32(float x) {
    uint32_t r; asm("cvt.rna.tf32.f32 %0, %1;" : "=r"(r) : "f"(x)); return r;
}
#define CP_ASYNC16(dst, src, sz) \
    asm volatile("cp.async.cg.shared.global [%0], [%1], 16, %2;" :: "r"(dst), "l"(src), "r"(sz) : "memory")
#define CP_COMMIT() asm volatile("cp.async.commit_group;" ::: "memory")
#define CP_WAIT0()  asm volatile("cp.async.wait_group 0;" ::: "memory")
#define CP_WAIT1()  asm volatile("cp.async.wait_group 1;" ::: "memory")
#define MMA_TF32(d, a, b) \
    asm volatile("mma.sync.aligned.m16n8k8.row.col.f32.tf32.tf32.f32 " \
        "{%0,%1,%2,%3}, {%4,%5,%6,%7}, {%8,%9}, {%0,%1,%2,%3};" \
        : "+f"((d)[0]), "+f"((d)[1]), "+f"((d)[2]), "+f"((d)[3]) \
        : "r"((a)[0]), "r"((a)[1]), "r"((a)[2]), "r"((a)[3]), "r"((b)[0]), "r"((b)[1]))

// C[M,N] = A[M,K] @ B[K,N] (+fused epilogue). 128x128x32 tiles, cp.async double buffer.
#define GEMM_SMEM 71680
__global__ void __launch_bounds__(256) gemm_tc(const float* __restrict__ A, const float* __restrict__ B,
                                               float* __restrict__ C, int M, int N, int K,
                                               const float* __restrict__ res, const float* __restrict__ mul, int epi)
{
    extern __shared__ float gs[];
    float (*As)[36]  = (float(*)[36])gs;                   // [2*128][36]
    float (*Bs)[136] = (float(*)[136])(gs + 2 * 128 * 36); // [2*32][136]
    int tid = threadIdx.x;
    int m0 = blockIdx.y * 128, n0 = blockIdx.x * 128;
    int w = tid >> 5, lane = tid & 31;
    int wm = (w >> 2) * 64;
    int wn = (w & 3) * 32;

    float acc[4][4][4];
    #pragma unroll
    for (int mi = 0; mi < 4; mi++)
        #pragma unroll
        for (int ni = 0; ni < 4; ni++)
            #pragma unroll
            for (int e = 0; e < 4; e++) acc[mi][ni][e] = 0.f;

    const int NC = K >> 5;

    auto fill = [&](int buf, int k0) {
        #pragma unroll
        for (int i = 0; i < 4; i++) {
            int task = tid + i * 256;
            int r = task >> 3, q = (task & 7) * 4;
            const float* src = A + (size_t)(m0 + r) * K + k0 + q;
            uint32_t dst = (uint32_t)__cvta_generic_to_shared(&As[buf * 128 + r][q]);
            CP_ASYNC16(dst, src, 16);
        }
        #pragma unroll
        for (int i = 0; i < 4; i++) {
            int task = tid + i * 256;
            int kk = task >> 5, c4 = (task & 31) * 4;
            int ok = (n0 + c4) < N;
            const float* src = B + (size_t)(k0 + kk) * N + (ok ? (n0 + c4) : 0);
            uint32_t dst = (uint32_t)__cvta_generic_to_shared(&Bs[buf * 32 + kk][c4]);
            CP_ASYNC16(dst, src, ok ? 16 : 0);
        }
    };

    fill(0, 0);
    CP_COMMIT();

    int arow = lane >> 2, acol = lane & 3;
    int bk = lane & 3, bn = lane >> 2;

    for (int ct = 0; ct < NC; ct++) {
        int buf = ct & 1;
        if (ct + 1 < NC) { fill(buf ^ 1, (ct + 1) * 32); CP_COMMIT(); CP_WAIT1(); }
        else             { CP_WAIT0(); }
        __syncthreads();

        const float (*as)[36]  = &As[buf * 128];
        const float (*bs)[136] = &Bs[buf * 32];
        #pragma unroll
        for (int ks = 0; ks < 4; ks++) {
            int kb = ks * 8;
            uint32_t af[4][4];
            #pragma unroll
            for (int mi = 0; mi < 4; mi++) {
                int r = wm + mi * 16 + arow;
                af[mi][0] = f2tf32(as[r][kb + acol]);
                af[mi][1] = f2tf32(as[r + 8][kb + acol]);
                af[mi][2] = f2tf32(as[r][kb + acol + 4]);
                af[mi][3] = f2tf32(as[r + 8][kb + acol + 4]);
            }
            uint32_t bf[4][2];
            #pragma unroll
            for (int ni = 0; ni < 4; ni++) {
                int c = wn + ni * 8 + bn;
                bf[ni][0] = f2tf32(bs[kb + bk][c]);
                bf[ni][1] = f2tf32(bs[kb + bk + 4][c]);
            }
            #pragma unroll
            for (int mi = 0; mi < 4; mi++)
                #pragma unroll
                for (int ni = 0; ni < 4; ni++)
                    MMA_TF32(acc[mi][ni], af[mi], bf[ni]);
        }
        __syncthreads();
    }

    #pragma unroll
    for (int mi = 0; mi < 4; mi++) {
        int r0 = m0 + wm + mi * 16 + (lane >> 2);
        #pragma unroll
        for (int ni = 0; ni < 4; ni++) {
            int c = n0 + wn + ni * 8 + (lane & 3) * 2;
            if (c < N) {
                #pragma unroll
                for (int half = 0; half < 2; half++) {
                    int r = r0 + half * 8;
                    size_t idx = (size_t)r * N + c;
                    float v0 = acc[mi][ni][half * 2 + 0];
                    float v1 = acc[mi][ni][half * 2 + 1];
                    if (epi == 1) {
                        v0 += res[idx]; v1 += res[idx + 1];
                    } else if (epi == 2) {
                        v0 = fmaxf(v0, 0.f); v0 *= v0;
                        v1 = fmaxf(v1, 0.f); v1 *= v1;
                    } else if (epi == 3) {
                        v0 = res[idx]     + mul[idx]     / (1.f + expf(-v0));
                        v1 = res[idx + 1] + mul[idx + 1] / (1.f + expf(-v1));
                    }
                    C[idx] = v0; C[idx + 1] = v1;
                }
            }
        }
    }
}

// ---------------- xBC causal depthwise conv (K=4) + silu ----------------
__global__ void conv_silu_k(const float* __restrict__ cw, const float* __restrict__ cb) {
    int bt = blockIdx.x; int b = bt >> 10, t = bt & 1023;
    for (int c = threadIdx.x; c < XBCD; c += blockDim.x) {
        float acc = cb[c];
        #pragma unroll
        for (int k = 0; k < 4; k++) {
            int tt = t + k - 3;
            if (tt >= 0) acc = fmaf(cw[c * 4 + k], g_zxb[(size_t)(b * TT + tt) * ZXB + DI + c], acc);
        }
        acc = acc / (1.f + expf(-acc));
        g_xBC[(size_t)bt * XBCD + c] = acc;
    }
}

__global__ void dt_k(const float* __restrict__ dt_bias, const float* __restrict__ A_log) {
    int i = blockIdx.x * blockDim.x + threadIdx.x;
    if (i >= BT * NH) return;
    int h = i & 31;
    float v = g_zxb[(size_t)(i >> 5) * ZXB + 4352 + h] + dt_bias[h];
    float sp = (v > 20.f) ? v : log1pf(expf(v));
    g_dt[i] = sp;
    g_dA[i] = expf(sp * (-expf(A_log[h])));
}

// ---------------- SSM scan ----------------
__global__ void scan_k() {
    int bid = blockIdx.x;
    int ns = bid & 1; int bh = bid >> 1; int b = bh >> 5; int h = bh & 31;
    int tid = threadIdx.x;
    int p = tid >> 3;
    int ng = tid & 7;
    __shared__ float sB[16 * 64], sC[16 * 64], sX[16 * 64], sS[16];
    float s[8];
    #pragma unroll
    for (int j = 0; j < 8; j++) s[j] = 0.f;
    int nb = ns * 64;

    for (int ct = 0; ct < TT / 16; ct++) {
        int t0 = ct * 16;
        #pragma unroll
        for (int l = 0; l < 2; l++) {
            int e = tid + l * 512; int tt = e >> 6; int n = e & 63;
            int base = b * TT + t0 + tt;
            sB[e] = g_xBC[(size_t)base * XBCD + DI + nb + n];
            sC[e] = g_xBC[(size_t)base * XBCD + DI + DS + nb + n];
            sX[e] = g_xBC[(size_t)base * XBCD + h * 64 + n] * g_dt[base * NH + h];
        }
        if (tid < 16) sS[tid] = g_dA[(b * TT + t0 + tid) * NH + h];
        __syncthreads();
        for (int tt = 0; tt < 16; tt++) {
            float da = sS[tt];
            float dtx = sX[tt * 64 + p];
            float bb[8], cc[8];
            *(float4*)&bb[0] = *(float4*)&sB[tt * 64 + ng * 8];
            *(float4*)&bb[4] = *(float4*)&sB[tt * 64 + ng * 8 + 4];
            *(float4*)&cc[0] = *(float4*)&sC[tt * 64 + ng * 8];
            *(float4*)&cc[4] = *(float4*)&sC[tt * 64 + ng * 8 + 4];
            float acc = 0.f;
            #pragma unroll
            for (int j = 0; j < 8; j++) {
                s[j] = fmaf(s[j], da, dtx * bb[j]);
                acc = fmaf(s[j], cc[j], acc);
            }
            acc += __shfl_xor_sync(0xffffffffu, acc, 1);
            acc += __shfl_xor_sync(0xffffffffu, acc, 2);
            acc += __shfl_xor_sync(0xffffffffu, acc, 4);
            if (ng == 0)
                g_yp[(size_t)ns * (BT * DI) + (size_t)(b * TT + t0 + tt) * DI + h * 64 + p] = acc;
        }
        __syncthreads();
    }
}

__global__ void gate_k(const float* __restrict__ Dm, const float* __restrict__ mnw) {
    int bt = blockIdx.x;
    float ss = 0.f;
    for (int c = threadIdx.x; c < DI; c += blockDim.x) {
        float v = g_yp[(size_t)bt * DI + c] + g_yp[(size_t)BT * DI + (size_t)bt * DI + c]
                + g_xBC[(size_t)bt * XBCD + c] * Dm[c >> 6];
        float z = g_zxb[(size_t)bt * ZXB + c];
        v *= z / (1.f + expf(-z));
        g_y2[(size_t)bt * DI + c] = v;
        ss = fmaf(v, v, ss);
    }
    ss = block_sum(ss);
    float sc = rsqrtf(ss / (float)DI + 1e-5f);
    for (int c = threadIdx.x; c < DI; c += blockDim.x)
        g_y2[(size_t)bt * DI + c] *= sc * mnw[c];
}

__global__ void convqkv_k(const float* __restrict__ qw, const float* __restrict__ qb,
                          const float* __restrict__ kw, const float* __restrict__ kb,
                          const float* __restrict__ vw, const float* __restrict__ vb) {
    int bt = blockIdx.x; int b = bt >> 10, t = bt & 1023;
    for (int c = threadIdx.x; c < QKVD; c += blockDim.x) {
        const float* w; const float* bias; int d;
        if (c < DM)            { d = c & 63;        w = qw; bias = qb; }
        else if (c < DM + 64)  { d = c - DM;        w = kw; bias = kb; }
        else                   { d = c - DM - 64;   w = vw; bias = vb; }
        float acc = bias[d];
        #pragma unroll
        for (int k = 0; k < 3; k++) {
            int tt = t + k - 2;
            if (tt >= 0) acc = fmaf(w[d * 3 + k], g_qkv[(size_t)(b * TT + tt) * QKVD + c], acc);
        }
        if (c < DM)           g_qc[(size_t)bt * DM + c] = acc;
        else if (c < DM + 64) g_kc[(size_t)bt * 64 + d] = acc;
        else                  g_vc[(size_t)bt * 64 + d] = acc;
    }
}

// ---------------- fused causal attention (tf32 mma, online softmax) ----------------
// grid: b*256 + h*16 + qb ; 128 threads = 4 warps, warp w owns q-rows w*16..w*16+15.
#define ATTN_SMEM 69632
__global__ void __launch_bounds__(128) attn_k() {
    extern __shared__ float sm[];
    float* qs = sm;              // [64][68] q rows x d   (pre-scaled by 1/8)
    float* ks = sm + 4352;       // [64][68] kt rows x d
    float* vT = sm + 8704;       // [64][68] d rows x kt  (V transposed)
    float* ps = sm + 13056;      // [64][68] q rows x kt  (P)
    int bid = blockIdx.x;
    int qb = bid & 15; int h = (bid >> 4) & 15; int b = bid >> 8;
    int tid = threadIdx.x;
    int w = tid >> 5, lane = tid & 31;
    int lr = lane >> 2, lc = lane & 3;

    // load Q tile (scaled)
    {
        int r = tid >> 1, d0 = (tid & 1) * 32;
        const float* qp = &g_qc[(size_t)(b * TT + qb * 64 + r) * DM + h * 64 + d0];
        #pragma unroll
        for (int j = 0; j < 8; j++) {
            float4 v = *(const float4*)(qp + j * 4);
            *(float4*)&qs[r * 68 + d0 + j * 4] =
                make_float4(v.x * 0.125f, v.y * 0.125f, v.z * 0.125f, v.w * 0.125f);
        }
    }

    float m[2] = {-1e30f, -1e30f}, l[2] = {0.f, 0.f};
    float o[8][4];
    #pragma unroll
    for (int ni = 0; ni < 8; ni++)
        #pragma unroll
        for (int e = 0; e < 4; e++) o[ni][e] = 0.f;

    for (int kb = 0; kb <= qb; kb++) {
        __syncthreads();
        {
            int r = tid >> 1, d0 = (tid & 1) * 32;
            const float* kp = &g_kc[(size_t)(b * TT + kb * 64 + r) * 64 + d0];
            const float* vp = &g_vc[(size_t)(b * TT + kb * 64 + r) * 64 + d0];
            #pragma unroll
            for (int j = 0; j < 8; j++) {
                *(float4*)&ks[r * 68 + d0 + j * 4] = *(const float4*)(kp + j * 4);
                float4 vv = *(const float4*)(vp + j * 4);
                int d = d0 + j * 4;
                vT[(d + 0) * 68 + r] = vv.x; vT[(d + 1) * 68 + r] = vv.y;
                vT[(d + 2) * 68 + r] = vv.z; vT[(d + 3) * 68 + r] = vv.w;
            }
        }
        __syncthreads();

        // S = Q @ K^T  (fragments: A row-major from qs, B col-major = ks[kt][d])
        float sc[8][4];
        #pragma unroll
        for (int ni = 0; ni < 8; ni++)
            #pragma unroll
            for (int e = 0; e < 4; e++) sc[ni][e] = 0.f;
        #pragma unroll
        for (int ksx = 0; ksx < 8; ksx++) {
            int k8 = ksx * 8;
            int r = w * 16 + lr;
            uint32_t af[4];
            af[0] = f2tf32(qs[r * 68 + k8 + lc]);
            af[1] = f2tf32(qs[(r + 8) * 68 + k8 + lc]);
            af[2] = f2tf32(qs[r * 68 + k8 + lc + 4]);
            af[3] = f2tf32(qs[(r + 8) * 68 + k8 + lc + 4]);
            #pragma unroll
            for (int ni = 0; ni < 8; ni++) {
                int n = ni * 8 + lr;
                uint32_t bf[2];
                bf[0] = f2tf32(ks[n * 68 + k8 + lc]);
                bf[1] = f2tf32(ks[n * 68 + k8 + lc + 4]);
                MMA_TF32(sc[ni], af, bf);
            }
        }

        // causal mask (diagonal tile only) + online softmax + store P
        bool diag = (kb == qb);
        #pragma unroll
        for (int h2 = 0; h2 < 2; h2++) {
            int row = w * 16 + lr + h2 * 8;       // row within tile
            if (diag) {
                #pragma unroll
                for (int ni = 0; ni < 8; ni++) {
                    int c0 = ni * 8 + lc * 2;
                    if (c0 > row)     sc[ni][h2 * 2 + 0] = -1e30f;
                    if (c0 + 1 > row) sc[ni][h2 * 2 + 1] = -1e30f;
                }
            }
            float mx = -1e30f;
            #pragma unroll
            for (int ni = 0; ni < 8; ni++)
                mx = fmaxf(mx, fmaxf(sc[ni][h2 * 2], sc[ni][h2 * 2 + 1]));
            mx = fmaxf(mx, __shfl_xor_sync(0xffffffffu, mx, 1));
            mx = fmaxf(mx, __shfl_xor_sync(0xffffffffu, mx, 2));
            float mn = fmaxf(m[h2], mx);
            float alpha = __expf(m[h2] - mn);
            m[h2] = mn;
            float rs = 0.f;
            #pragma unroll
            for (int ni = 0; ni < 8; ni++) {
                float p0 = __expf(sc[ni][h2 * 2]     - mn);
                float p1 = __expf(sc[ni][h2 * 2 + 1] - mn);
                sc[ni][h2 * 2] = p0; sc[ni][h2 * 2 + 1] = p1;
                rs += p0 + p1;
                *(float2*)&ps[row * 68 + ni * 8 + lc * 2] = make_float2(p0, p1);
            }
            rs += __shfl_xor_sync(0xffffffffu, rs, 1);
            rs += __shfl_xor_sync(0xffffffffu, rs, 2);
            l[h2] = l[h2] * alpha + rs;
            #pragma unroll
            for (int ni = 0; ni < 8; ni++) {
                o[ni][h2 * 2]     *= alpha;
                o[ni][h2 * 2 + 1] *= alpha;
            }
        }
        __syncwarp();   // warp reads only its own P rows

        // O += P @ V  (A from ps, B col-major = vT[d][kt])
        #pragma unroll
        for (int ksx = 0; ksx < 8; ksx++) {
            int k8 = ksx * 8;
            int r = w * 16 + lr;
            uint32_t af[4];
            af[0] = f2tf32(ps[r * 68 + k8 + lc]);
            af[1] = f2tf32(ps[(r + 8) * 68 + k8 + lc]);
            af[2] = f2tf32(ps[r * 68 + k8 + lc + 4]);
            af[3] = f2tf32(ps[(r + 8) * 68 + k8 + lc + 4]);
            #pragma unroll
            for (int ni = 0; ni < 8; ni++) {
                int n = ni * 8 + lr;
                uint32_t bf[2];
                bf[0] = f2tf32(vT[n * 68 + k8 + lc]);
                bf[1] = f2tf32(vT[n * 68 + k8 + lc + 4]);
                MMA_TF32(o[ni], af, bf);
            }
        }
    }

    #pragma unroll
    for (int h2 = 0; h2 < 2; h2++) {
        float inv = 1.f / l[h2];
        int r = qb * 64 + w * 16 + lr + h2 * 8;
        #pragma unroll
        for (int ni = 0; ni < 8; ni++) {
            float2 v = make_float2(o[ni][h2 * 2] * inv, o[ni][h2 * 2 + 1] * inv);
            *(float2*)&g_att[(size_t)(b * TT + r) * DM + h * 64 + ni * 8 + lc * 2] = v;
        }
    }
}

__global__ void shift_k(const float* __restrict__ tmk, const float* __restrict__ tmr) {
    int i = blockIdx.x * blockDim.x + threadIdx.x;
    if (i >= BT * DM) return;
    int c = i & 1023; int t = (i >> 10) & 1023;
    float cur = g_h[i];
    float prev = t ? g_h[i - DM] : 0.f;
    float dd = prev - cur;
    g_xk[i] = fmaf(dd, tmk[c], cur);
    g_xr[i] = fmaf(dd, tmr[c], cur);
}

// ---------------- host launch ----------------
static void run_gemm(const float* A, const float* W, float* C, int M, int N, int K,
                     const float* res, const float* mul, int epi) {
    gemm_tc<<<dim3((N + 127) / 128, M / 128), 256, GEMM_SMEM>>>(A, W, C, M, N, K, res, mul, epi);
}

extern "C" void kernel_launch(void* const* d_in, const int* in_sizes, int n_in,
                              void* d_out, int out_size) {
    const float* x       = (const float*)d_in[0];
    const float* W_in    = (const float*)d_in[1];
    const float* conv_w  = (const float*)d_in[2];
    const float* conv_b  = (const float*)d_in[3];
    const float* A_log   = (const float*)d_in[4];
    const float* Dm      = (const float*)d_in[5];
    const float* dt_bias = (const float*)d_in[6];
    const float* mnorm_w = (const float*)d_in[7];
    const float* W_out   = (const float*)d_in[8];
    const float* W_qkv   = (const float*)d_in[9];
    const float* W_cproj = (const float*)d_in[10];
    const float* qconv_w = (const float*)d_in[11];
    const float* qconv_b = (const float*)d_in[12];
    const float* kconv_w = (const float*)d_in[13];
    const float* kconv_b = (const float*)d_in[14];
    const float* vconv_w = (const float*)d_in[15];
    const float* vconv_b = (const float*)d_in[16];
    const float* tmk     = (const float*)d_in[17];
    const float* tmr     = (const float*)d_in[18];
    const float* W_key   = (const float*)d_in[19];
    const float* W_rec   = (const float*)d_in[20];
    const float* W_val   = (const float*)d_in[21];
    float* out = (float*)d_out;

    float *p_h, *p_zxb, *p_y2, *p_x2, *p_qkv, *p_att, *p_x3, *p_xk, *p_xr, *p_kf, *p_kv;
    cudaGetSymbolAddress((void**)&p_h, g_h);
    cudaGetSymbolAddress((void**)&p_zxb, g_zxb);
    cudaGetSymbolAddress((void**)&p_y2, g_y2);
    cudaGetSymbolAddress((void**)&p_x2, g_x2);
    cudaGetSymbolAddress((void**)&p_qkv, g_qkv);
    cudaGetSymbolAddress((void**)&p_att, g_att);
    cudaGetSymbolAddress((void**)&p_x3, g_x3);
    cudaGetSymbolAddress((void**)&p_xk, g_xk);
    cudaGetSymbolAddress((void**)&p_xr, g_xr);
    cudaGetSymbolAddress((void**)&p_kf, g_kf);
    cudaGetSymbolAddress((void**)&p_kv, g_kv);

    cudaFuncSetAttribute(attn_k, cudaFuncAttributeMaxDynamicSharedMemorySize, ATTN_SMEM);
    cudaFuncSetAttribute(gemm_tc, cudaFuncAttributeMaxDynamicSharedMemorySize, GEMM_SMEM);

    // ---- Mamba2-style block ----
    rmsnorm_k<<<BT, 256>>>(x, p_h, 1e-6f);
    run_gemm(p_h, W_in, p_zxb, BT, ZXB, DM, nullptr, nullptr, 0);
    conv_silu_k<<<BT, 256>>>(conv_w, conv_b);
    dt_k<<<(BT * NH + 255) / 256, 256>>>(dt_bias, A_log);
    scan_k<<<128, 512>>>();
    gate_k<<<BT, 256>>>(Dm, mnorm_w);
    run_gemm(p_y2, W_out, p_x2, BT, DM, DI, x, nullptr, 1);

    // ---- attention block ----
    rmsnorm_k<<<BT, 256>>>(p_x2, p_h, 1e-6f);
    run_gemm(p_h, W_qkv, p_qkv, BT, QKVD, DM, nullptr, nullptr, 0);
    convqkv_k<<<BT, 256>>>(qconv_w, qconv_b, kconv_w, kconv_b, vconv_w, vconv_b);
    attn_k<<<BSZ * NHA * (TT / 64), 128, ATTN_SMEM>>>();
    run_gemm(p_att, W_cproj, p_x3, BT, DM, DM, p_x2, nullptr, 1);

    // ---- channel mix ----
    rmsnorm_k<<<BT, 256>>>(p_x3, p_h, 1e-6f);
    shift_k<<<(BT * DM + 255) / 256, 256>>>(tmk, tmr);
    run_gemm(p_xk, W_key, p_kf, BT, FFND, DM, nullptr, nullptr, 2);
    run_gemm(p_kf, W_val, p_kv, BT, DM, FFND, nullptr, nullptr, 0);
    run_gemm(p_xr, W_rec, out, BT, DM, DM, p_x3, p_kv, 3);
}

// round 8
// speedup vs baseline: 2.7823x; 1.0464x over previous
#include <cuda_runtime.h>
#include <math.h>
#include <stdint.h>

#define BSZ 2
#define TT 1024
#define DM 1024
#define DI 2048
#define DS 128
#define NH 32
#define HDS 64
#define NHA 16
#define HDA 64
#define FFND 4096
#define ZXB 4384
#define XBCD 2304
#define QKVD 1152
#define BT (BSZ*TT)

// ---------------- scratch (device globals; no allocations allowed) ----------------
__device__ float g_h[BT*DM];
__device__ float g_zxb[BT*ZXB];
__device__ float g_xBC[BT*XBCD];
__device__ float g_dt[BT*NH];
__device__ float g_dA[BT*NH];
__device__ float g_yp[2*BT*DI];
__device__ float g_y2[BT*DI];
__device__ float g_x2[BT*DM];
__device__ float g_qkv[BT*QKVD];
__device__ float g_qc[BT*DM];
__device__ float g_kc[BT*HDA];
__device__ float g_vc[BT*HDA];
__device__ float g_att[BT*DM];
__device__ float g_x3[BT*DM];
__device__ float g_xk[BT*DM];
__device__ float g_xr[BT*DM];
__device__ float g_kf[BT*FFND];
__device__ float g_kv[BT*DM];
__device__ float g_wt[18251776];   // tf32-rounded weights (73MB)

// weight offsets in g_wt
#define OW_IN    0
#define OW_OUT   4489216
#define OW_QKV   6586368
#define OW_CPROJ 7766016
#define OW_KEY   8814592
#define OW_VAL   13008896
#define OW_REC   17203200

// ---------------- helpers ----------------
__device__ __forceinline__ uint32_t f2tf32(float x) {
    uint32_t r; asm("cvt.rna.tf32.f32 %0, %1;" : "=r"(r) : "f"(x)); return r;
}
__device__ __forceinline__ float tf32r(float x) { return __uint_as_float(f2tf32(x)); }

__device__ __forceinline__ float block_sum(float v) {
    __shared__ float red[32];
    int lane = threadIdx.x & 31, w = threadIdx.x >> 5;
    #pragma unroll
    for (int o = 16; o; o >>= 1) v += __shfl_xor_sync(0xffffffffu, v, o);
    if (lane == 0) red[w] = v;
    __syncthreads();
    int nw = blockDim.x >> 5;
    float r = (threadIdx.x < nw) ? red[threadIdx.x] : 0.f;
    if (w == 0) {
        #pragma unroll
        for (int o = 16; o; o >>= 1) r += __shfl_xor_sync(0xffffffffu, r, o);
        if (lane == 0) red[0] = r;
    }
    __syncthreads();
    return red[0];
}

// rnd=1: round output to tf32 (when consumed as GEMM A operand)
__global__ void rmsnorm_k(const float* __restrict__ x, float* __restrict__ o, float eps, int rnd) {
    int row = blockIdx.x;
    const float* xr = x + (size_t)row * DM;
    float ss = 0.f;
    for (int c = threadIdx.x; c < DM; c += blockDim.x) { float v = xr[c]; ss = fmaf(v, v, ss); }
    ss = block_sum(ss);
    float sc = rsqrtf(ss / (float)DM + eps);
    float* orow = o + (size_t)row * DM;
    if (rnd) for (int c = threadIdx.x; c < DM; c += blockDim.x) orow[c] = tf32r(xr[c] * sc);
    else     for (int c = threadIdx.x; c < DM; c += blockDim.x) orow[c] = xr[c] * sc;
}

// ---------------- weight tf32 pre-round ----------------
__global__ void cvtw_k(const float* __restrict__ in, float* __restrict__ out, int n) {
    int i = (blockIdx.x * blockDim.x + threadIdx.x) * 4;
    if (i < n) {
        float4 v = *(const float4*)(in + i);
        v.x = tf32r(v.x); v.y = tf32r(v.y); v.z = tf32r(v.z); v.w = tf32r(v.w);
        *(float4*)(out + i) = v;
    }
}

// ================= tf32 mma.sync GEMM =================
#define CP_ASYNC16(dst, src, sz) \
    asm volatile("cp.async.cg.shared.global [%0], [%1], 16, %2;" :: "r"(dst), "l"(src), "r"(sz) : "memory")
#define CP_COMMIT() asm volatile("cp.async.commit_group;" ::: "memory")
#define CP_WAIT0()  asm volatile("cp.async.wait_group 0;" ::: "memory")
#define CP_WAIT1()  asm volatile("cp.async.wait_group 1;" ::: "memory")
#define MMA_TF32(d, a, b) \
    asm volatile("mma.sync.aligned.m16n8k8.row.col.f32.tf32.tf32.f32 " \
        "{%0,%1,%2,%3}, {%4,%5,%6,%7}, {%8,%9}, {%0,%1,%2,%3};" \
        : "+f"((d)[0]), "+f"((d)[1]), "+f"((d)[2]), "+f"((d)[3]) \
        : "r"((a)[0]), "r"((a)[1]), "r"((a)[2]), "r"((a)[3]), "r"((b)[0]), "r"((b)[1]))

// C[M,N] = A[M,K] @ B[K,N] (+fused epilogue). A and B are PRE-ROUNDED to tf32.
#define GEMM_SMEM 71680
__global__ void __launch_bounds__(256) gemm_tc(const float* __restrict__ A, const float* __restrict__ B,
                                               float* __restrict__ C, int M, int N, int K,
                                               const float* __restrict__ res, const float* __restrict__ mul, int epi)
{
    extern __shared__ float gs[];
    float (*As)[36]  = (float(*)[36])gs;                   // [2*128][36]
    float (*Bs)[136] = (float(*)[136])(gs + 2 * 128 * 36); // [2*32][136]
    int tid = threadIdx.x;
    int m0 = blockIdx.y * 128, n0 = blockIdx.x * 128;
    int w = tid >> 5, lane = tid & 31;
    int wm = (w >> 2) * 64;
    int wn = (w & 3) * 32;

    float acc[4][4][4];
    #pragma unroll
    for (int mi = 0; mi < 4; mi++)
        #pragma unroll
        for (int ni = 0; ni < 4; ni++)
            #pragma unroll
            for (int e = 0; e < 4; e++) acc[mi][ni][e] = 0.f;

    const int NC = K >> 5;

    auto fill = [&](int buf, int k0) {
        #pragma unroll
        for (int i = 0; i < 4; i++) {
            int task = tid + i * 256;
            int r = task >> 3, q = (task & 7) * 4;
            const float* src = A + (size_t)(m0 + r) * K + k0 + q;
            uint32_t dst = (uint32_t)__cvta_generic_to_shared(&As[buf * 128 + r][q]);
            CP_ASYNC16(dst, src, 16);
        }
        #pragma unroll
        for (int i = 0; i < 4; i++) {
            int task = tid + i * 256;
            int kk = task >> 5, c4 = (task & 31) * 4;
            int ok = (n0 + c4) < N;
            const float* src = B + (size_t)(k0 + kk) * N + (ok ? (n0 + c4) : 0);
            uint32_t dst = (uint32_t)__cvta_generic_to_shared(&Bs[buf * 32 + kk][c4]);
            CP_ASYNC16(dst, src, ok ? 16 : 0);
        }
    };

    fill(0, 0);
    CP_COMMIT();

    int arow = lane >> 2, acol = lane & 3;
    int bk = lane & 3, bn = lane >> 2;

    for (int ct = 0; ct < NC; ct++) {
        int buf = ct & 1;
        if (ct + 1 < NC) { fill(buf ^ 1, (ct + 1) * 32); CP_COMMIT(); CP_WAIT1(); }
        else             { CP_WAIT0(); }
        __syncthreads();

        const float (*as)[36]  = &As[buf * 128];
        const float (*bs)[136] = &Bs[buf * 32];
        #pragma unroll
        for (int ks = 0; ks < 4; ks++) {
            int kb = ks * 8;
            uint32_t af[4][4];
            #pragma unroll
            for (int mi = 0; mi < 4; mi++) {
                int r = wm + mi * 16 + arow;
                af[mi][0] = __float_as_uint(as[r][kb + acol]);
                af[mi][1] = __float_as_uint(as[r + 8][kb + acol]);
                af[mi][2] = __float_as_uint(as[r][kb + acol + 4]);
                af[mi][3] = __float_as_uint(as[r + 8][kb + acol + 4]);
            }
            uint32_t bf[4][2];
            #pragma unroll
            for (int ni = 0; ni < 4; ni++) {
                int c = wn + ni * 8 + bn;
                bf[ni][0] = __float_as_uint(bs[kb + bk][c]);
                bf[ni][1] = __float_as_uint(bs[kb + bk + 4][c]);
            }
            #pragma unroll
            for (int mi = 0; mi < 4; mi++)
                #pragma unroll
                for (int ni = 0; ni < 4; ni++)
                    MMA_TF32(acc[mi][ni], af[mi], bf[ni]);
        }
        __syncthreads();
    }

    #pragma unroll
    for (int mi = 0; mi < 4; mi++) {
        int r0 = m0 + wm + mi * 16 + (lane >> 2);
        #pragma unroll
        for (int ni = 0; ni < 4; ni++) {
            int c = n0 + wn + ni * 8 + (lane & 3) * 2;
            if (c < N) {
                #pragma unroll
                for (int half = 0; half < 2; half++) {
                    int r = r0 + half * 8;
                    size_t idx = (size_t)r * N + c;
                    float v0 = acc[mi][ni][half * 2 + 0];
                    float v1 = acc[mi][ni][half * 2 + 1];
                    if (epi == 1) {
                        v0 += res[idx]; v1 += res[idx + 1];
                    } else if (epi == 2) {
                        v0 = fmaxf(v0, 0.f); v0 = tf32r(v0 * v0);   // feeds W_val GEMM as A
                        v1 = fmaxf(v1, 0.f); v1 = tf32r(v1 * v1);
                    } else if (epi == 3) {
                        v0 = res[idx]     + mul[idx]     / (1.f + expf(-v0));
                        v1 = res[idx + 1] + mul[idx + 1] / (1.f + expf(-v1));
                    }
                    C[idx] = v0; C[idx + 1] = v1;
                }
            }
        }
    }
}

// ---------------- xBC causal depthwise conv (K=4) + silu ----------------
__global__ void conv_silu_k(const float* __restrict__ cw, const float* __restrict__ cb) {
    int bt = blockIdx.x; int b = bt >> 10, t = bt & 1023;
    for (int c = threadIdx.x; c < XBCD; c += blockDim.x) {
        float acc = cb[c];
        #pragma unroll
        for (int k = 0; k < 4; k++) {
            int tt = t + k - 3;
            if (tt >= 0) acc = fmaf(cw[c * 4 + k], g_zxb[(size_t)(b * TT + tt) * ZXB + DI + c], acc);
        }
        acc = acc / (1.f + expf(-acc));
        g_xBC[(size_t)bt * XBCD + c] = acc;
    }
}

__global__ void dt_k(const float* __restrict__ dt_bias, const float* __restrict__ A_log) {
    int i = blockIdx.x * blockDim.x + threadIdx.x;
    if (i >= BT * NH) return;
    int h = i & 31;
    float v = g_zxb[(size_t)(i >> 5) * ZXB + 4352 + h] + dt_bias[h];
    float sp = (v > 20.f) ? v : log1pf(expf(v));
    g_dt[i] = sp;
    g_dA[i] = expf(sp * (-expf(A_log[h])));
}

// ---------------- SSM scan ----------------
__global__ void scan_k() {
    int bid = blockIdx.x;
    int ns = bid & 1; int bh = bid >> 1; int b = bh >> 5; int h = bh & 31;
    int tid = threadIdx.x;
    int p = tid >> 3;
    int ng = tid & 7;
    __shared__ float sB[16 * 64], sC[16 * 64], sX[16 * 64], sS[16];
    float s[8];
    #pragma unroll
    for (int j = 0; j < 8; j++) s[j] = 0.f;
    int nb = ns * 64;

    for (int ct = 0; ct < TT / 16; ct++) {
        int t0 = ct * 16;
        #pragma unroll
        for (int l = 0; l < 2; l++) {
            int e = tid + l * 512; int tt = e >> 6; int n = e & 63;
            int base = b * TT + t0 + tt;
            sB[e] = g_xBC[(size_t)base * XBCD + DI + nb + n];
            sC[e] = g_xBC[(size_t)base * XBCD + DI + DS + nb + n];
            sX[e] = g_xBC[(size_t)base * XBCD + h * 64 + n] * g_dt[base * NH + h];
        }
        if (tid < 16) sS[tid] = g_dA[(b * TT + t0 + tid) * NH + h];
        __syncthreads();
        for (int tt = 0; tt < 16; tt++) {
            float da = sS[tt];
            float dtx = sX[tt * 64 + p];
            float bb[8], cc[8];
            *(float4*)&bb[0] = *(float4*)&sB[tt * 64 + ng * 8];
            *(float4*)&bb[4] = *(float4*)&sB[tt * 64 + ng * 8 + 4];
            *(float4*)&cc[0] = *(float4*)&sC[tt * 64 + ng * 8];
            *(float4*)&cc[4] = *(float4*)&sC[tt * 64 + ng * 8 + 4];
            float acc = 0.f;
            #pragma unroll
            for (int j = 0; j < 8; j++) {
                s[j] = fmaf(s[j], da, dtx * bb[j]);
                acc = fmaf(s[j], cc[j], acc);
            }
            acc += __shfl_xor_sync(0xffffffffu, acc, 1);
            acc += __shfl_xor_sync(0xffffffffu, acc, 2);
            acc += __shfl_xor_sync(0xffffffffu, acc, 4);
            if (ng == 0)
                g_yp[(size_t)ns * (BT * DI) + (size_t)(b * TT + t0 + tt) * DI + h * 64 + p] = acc;
        }
        __syncthreads();
    }
}

__global__ void gate_k(const float* __restrict__ Dm, const float* __restrict__ mnw) {
    int bt = blockIdx.x;
    float ss = 0.f;
    for (int c = threadIdx.x; c < DI; c += blockDim.x) {
        float v = g_yp[(size_t)bt * DI + c] + g_yp[(size_t)BT * DI + (size_t)bt * DI + c]
                + g_xBC[(size_t)bt * XBCD + c] * Dm[c >> 6];
        float z = g_zxb[(size_t)bt * ZXB + c];
        v *= z / (1.f + expf(-z));
        g_y2[(size_t)bt * DI + c] = v;
        ss = fmaf(v, v, ss);
    }
    ss = block_sum(ss);
    float sc = rsqrtf(ss / (float)DI + 1e-5f);
    for (int c = threadIdx.x; c < DI; c += blockDim.x)
        g_y2[(size_t)bt * DI + c] = tf32r(g_y2[(size_t)bt * DI + c] * sc * mnw[c]);
}

__global__ void convqkv_k(const float* __restrict__ qw, const float* __restrict__ qb,
                          const float* __restrict__ kw, const float* __restrict__ kb,
                          const float* __restrict__ vw, const float* __restrict__ vb) {
    int bt = blockIdx.x; int b = bt >> 10, t = bt & 1023;
    for (int c = threadIdx.x; c < QKVD; c += blockDim.x) {
        const float* w; const float* bias; int d;
        if (c < DM)            { d = c & 63;        w = qw; bias = qb; }
        else if (c < DM + 64)  { d = c - DM;        w = kw; bias = kb; }
        else                   { d = c - DM - 64;   w = vw; bias = vb; }
        float acc = bias[d];
        #pragma unroll
        for (int k = 0; k < 3; k++) {
            int tt = t + k - 2;
            if (tt >= 0) acc = fmaf(w[d * 3 + k], g_qkv[(size_t)(b * TT + tt) * QKVD + c], acc);
        }
        if (c < DM)           g_qc[(size_t)bt * DM + c] = acc;
        else if (c < DM + 64) g_kc[(size_t)bt * 64 + d] = acc;
        else                  g_vc[(size_t)bt * 64 + d] = acc;
    }
}

// ---------------- fused causal attention (tf32 mma, online softmax) ----------------
// grid: b*256 + h*16 + qb ; 128 threads = 4 warps, warp w owns q-rows w*16..w*16+15.
// All smem tiles hold tf32-rounded values; inner loops do raw-bit LDS only.
#define ATTN_SMEM 69632
__global__ void __launch_bounds__(128) attn_k() {
    extern __shared__ float sm[];
    float* qs = sm;              // [64][68] q rows x d   (pre-scaled by 1/8, tf32)
    float* ks = sm + 4352;       // [64][68] kt rows x d  (tf32)
    float* vT = sm + 8704;       // [64][68] d rows x kt  (V transposed, tf32)
    float* ps = sm + 13056;      // [64][68] q rows x kt  (P, tf32)
    int bid = blockIdx.x;
    int qb = bid & 15; int h = (bid >> 4) & 15; int b = bid >> 8;
    int tid = threadIdx.x;
    int w = tid >> 5, lane = tid & 31;
    int lr = lane >> 2, lc = lane & 3;

    // load Q tile (scaled + rounded)
    {
        int r = tid >> 1, d0 = (tid & 1) * 32;
        const float* qp = &g_qc[(size_t)(b * TT + qb * 64 + r) * DM + h * 64 + d0];
        #pragma unroll
        for (int j = 0; j < 8; j++) {
            float4 v = *(const float4*)(qp + j * 4);
            *(float4*)&qs[r * 68 + d0 + j * 4] =
                make_float4(tf32r(v.x * 0.125f), tf32r(v.y * 0.125f),
                            tf32r(v.z * 0.125f), tf32r(v.w * 0.125f));
        }
    }

    float m[2] = {-1e30f, -1e30f}, l[2] = {0.f, 0.f};
    float o[8][4];
    #pragma unroll
    for (int ni = 0; ni < 8; ni++)
        #pragma unroll
        for (int e = 0; e < 4; e++) o[ni][e] = 0.f;

    for (int kb = 0; kb <= qb; kb++) {
        __syncthreads();
        {
            int r = tid >> 1, d0 = (tid & 1) * 32;
            const float* kp = &g_kc[(size_t)(b * TT + kb * 64 + r) * 64 + d0];
            const float* vp = &g_vc[(size_t)(b * TT + kb * 64 + r) * 64 + d0];
            #pragma unroll
            for (int j = 0; j < 8; j++) {
                float4 kv = *(const float4*)(kp + j * 4);
                *(float4*)&ks[r * 68 + d0 + j * 4] =
                    make_float4(tf32r(kv.x), tf32r(kv.y), tf32r(kv.z), tf32r(kv.w));
                float4 vv = *(const float4*)(vp + j * 4);
                int d = d0 + j * 4;
                vT[(d + 0) * 68 + r] = tf32r(vv.x); vT[(d + 1) * 68 + r] = tf32r(vv.y);
                vT[(d + 2) * 68 + r] = tf32r(vv.z); vT[(d + 3) * 68 + r] = tf32r(vv.w);
            }
        }
        __syncthreads();

        // S = Q @ K^T
        float sc[8][4];
        #pragma unroll
        for (int ni = 0; ni < 8; ni++)
            #pragma unroll
            for (int e = 0; e < 4; e++) sc[ni][e] = 0.f;
        #pragma unroll
        for (int ksx = 0; ksx < 8; ksx++) {
            int k8 = ksx * 8;
            int r = w * 16 + lr;
            uint32_t af[4];
            af[0] = __float_as_uint(qs[r * 68 + k8 + lc]);
            af[1] = __float_as_uint(qs[(r + 8) * 68 + k8 + lc]);
            af[2] = __float_as_uint(qs[r * 68 + k8 + lc + 4]);
            af[3] = __float_as_uint(qs[(r + 8) * 68 + k8 + lc + 4]);
            #pragma unroll
            for (int ni = 0; ni < 8; ni++) {
                int n = ni * 8 + lr;
                uint32_t bf[2];
                bf[0] = __float_as_uint(ks[n * 68 + k8 + lc]);
                bf[1] = __float_as_uint(ks[n * 68 + k8 + lc + 4]);
                MMA_TF32(sc[ni], af, bf);
            }
        }

        // causal mask (diagonal tile only) + online softmax + store P (tf32)
        bool diag = (kb == qb);
        #pragma unroll
        for (int h2 = 0; h2 < 2; h2++) {
            int row = w * 16 + lr + h2 * 8;
            if (diag) {
                #pragma unroll
                for (int ni = 0; ni < 8; ni++) {
                    int c0 = ni * 8 + lc * 2;
                    if (c0 > row)     sc[ni][h2 * 2 + 0] = -1e30f;
                    if (c0 + 1 > row) sc[ni][h2 * 2 + 1] = -1e30f;
                }
            }
            float mx = -1e30f;
            #pragma unroll
            for (int ni = 0; ni < 8; ni++)
                mx = fmaxf(mx, fmaxf(sc[ni][h2 * 2], sc[ni][h2 * 2 + 1]));
            mx = fmaxf(mx, __shfl_xor_sync(0xffffffffu, mx, 1));
            mx = fmaxf(mx, __shfl_xor_sync(0xffffffffu, mx, 2));
            float mn = fmaxf(m[h2], mx);
            float alpha = __expf(m[h2] - mn);
            m[h2] = mn;
            float rs = 0.f;
            #pragma unroll
            for (int ni = 0; ni < 8; ni++) {
                float p0 = __expf(sc[ni][h2 * 2]     - mn);
                float p1 = __expf(sc[ni][h2 * 2 + 1] - mn);
                rs += p0 + p1;
                *(float2*)&ps[row * 68 + ni * 8 + lc * 2] = make_float2(tf32r(p0), tf32r(p1));
            }
            rs += __shfl_xor_sync(0xffffffffu, rs, 1);
            rs += __shfl_xor_sync(0xffffffffu, rs, 2);
            l[h2] = l[h2] * alpha + rs;
            #pragma unroll
            for (int ni = 0; ni < 8; ni++) {
                o[ni][h2 * 2]     *= alpha;
                o[ni][h2 * 2 + 1] *= alpha;
            }
        }
        __syncwarp();

        // O += P @ V
        #pragma unroll
        for (int ksx = 0; ksx < 8; ksx++) {
            int k8 = ksx * 8;
            int r = w * 16 + lr;
            uint32_t af[4];
            af[0] = __float_as_uint(ps[r * 68 + k8 + lc]);
            af[1] = __float_as_uint(ps[(r + 8) * 68 + k8 + lc]);
            af[2] = __float_as_uint(ps[r * 68 + k8 + lc + 4]);
            af[3] = __float_as_uint(ps[(r + 8) * 68 + k8 + lc + 4]);
            #pragma unroll
            for (int ni = 0; ni < 8; ni++) {
                int n = ni * 8 + lr;
                uint32_t bf[2];
                bf[0] = __float_as_uint(vT[n * 68 + k8 + lc]);
                bf[1] = __float_as_uint(vT[n * 68 + k8 + lc + 4]);
                MMA_TF32(o[ni], af, bf);
            }
        }
    }

    #pragma unroll
    for (int h2 = 0; h2 < 2; h2++) {
        float inv = 1.f / l[h2];
        int r = qb * 64 + w * 16 + lr + h2 * 8;
        #pragma unroll
        for (int ni = 0; ni < 8; ni++) {
            // g_att feeds the W_cproj GEMM as A -> round here
            float2 v = make_float2(tf32r(o[ni][h2 * 2] * inv), tf32r(o[ni][h2 * 2 + 1] * inv));
            *(float2*)&g_att[(size_t)(b * TT + r) * DM + h * 64 + ni * 8 + lc * 2] = v;
        }
    }
}

__global__ void shift_k(const float* __restrict__ tmk, const float* __restrict__ tmr) {
    int i = blockIdx.x * blockDim.x + threadIdx.x;
    if (i >= BT * DM) return;
    int c = i & 1023; int t = (i >> 10) & 1023;
    float cur = g_h[i];
    float prev = t ? g_h[i - DM] : 0.f;
    float dd = prev - cur;
    g_xk[i] = tf32r(fmaf(dd, tmk[c], cur));
    g_xr[i] = tf32r(fmaf(dd, tmr[c], cur));
}

// ---------------- host launch ----------------
static void run_gemm(const float* A, const float* W, float* C, int M, int N, int K,
                     const float* res, const float* mul, int epi) {
    gemm_tc<<<dim3((N + 127) / 128, M / 128), 256, GEMM_SMEM>>>(A, W, C, M, N, K, res, mul, epi);
}

extern "C" void kernel_launch(void* const* d_in, const int* in_sizes, int n_in,
                              void* d_out, int out_size) {
    const float* x       = (const float*)d_in[0];
    const float* W_in    = (const float*)d_in[1];
    const float* conv_w  = (const float*)d_in[2];
    const float* conv_b  = (const float*)d_in[3];
    const float* A_log   = (const float*)d_in[4];
    const float* Dm      = (const float*)d_in[5];
    const float* dt_bias = (const float*)d_in[6];
    const float* mnorm_w = (const float*)d_in[7];
    const float* W_out   = (const float*)d_in[8];
    const float* W_qkv   = (const float*)d_in[9];
    const float* W_cproj = (const float*)d_in[10];
    const float* qconv_w = (const float*)d_in[11];
    const float* qconv_b = (const float*)d_in[12];
    const float* kconv_w = (const float*)d_in[13];
    const float* kconv_b = (const float*)d_in[14];
    const float* vconv_w = (const float*)d_in[15];
    const float* vconv_b = (const float*)d_in[16];
    const float* tmk     = (const float*)d_in[17];
    const float* tmr     = (const float*)d_in[18];
    const float* W_key   = (const float*)d_in[19];
    const float* W_rec   = (const float*)d_in[20];
    const float* W_val   = (const float*)d_in[21];
    float* out = (float*)d_out;

    float *p_h, *p_zxb, *p_y2, *p_x2, *p_qkv, *p_att, *p_x3, *p_xk, *p_xr, *p_kf, *p_kv, *p_wt;
    cudaGetSymbolAddress((void**)&p_h, g_h);
    cudaGetSymbolAddress((void**)&p_zxb, g_zxb);
    cudaGetSymbolAddress((void**)&p_y2, g_y2);
    cudaGetSymbolAddress((void**)&p_x2, g_x2);
    cudaGetSymbolAddress((void**)&p_qkv, g_qkv);
    cudaGetSymbolAddress((void**)&p_att, g_att);
    cudaGetSymbolAddress((void**)&p_x3, g_x3);
    cudaGetSymbolAddress((void**)&p_xk, g_xk);
    cudaGetSymbolAddress((void**)&p_xr, g_xr);
    cudaGetSymbolAddress((void**)&p_kf, g_kf);
    cudaGetSymbolAddress((void**)&p_kv, g_kv);
    cudaGetSymbolAddress((void**)&p_wt, g_wt);

    cudaFuncSetAttribute(attn_k, cudaFuncAttributeMaxDynamicSharedMemorySize, ATTN_SMEM);
    cudaFuncSetAttribute(gemm_tc, cudaFuncAttributeMaxDynamicSharedMemorySize, GEMM_SMEM);

    // ---- weight tf32 pre-round ----
    auto cvtw = [&](const float* src, int off, int n) {
        cvtw_k<<<(n / 4 + 255) / 256, 256>>>(src, p_wt + off, n);
    };
    cvtw(W_in,    OW_IN,    DM * ZXB);
    cvtw(W_out,   OW_OUT,   DI * DM);
    cvtw(W_qkv,   OW_QKV,   DM * QKVD);
    cvtw(W_cproj, OW_CPROJ, DM * DM);
    cvtw(W_key,   OW_KEY,   DM * FFND);
    cvtw(W_val,   OW_VAL,   FFND * DM);
    cvtw(W_rec,   OW_REC,   DM * DM);

    // ---- Mamba2-style block ----
    rmsnorm_k<<<BT, 256>>>(x, p_h, 1e-6f, 1);
    run_gemm(p_h, p_wt + OW_IN, p_zxb, BT, ZXB, DM, nullptr, nullptr, 0);
    conv_silu_k<<<BT, 256>>>(conv_w, conv_b);
    dt_k<<<(BT * NH + 255) / 256, 256>>>(dt_bias, A_log);
    scan_k<<<128, 512>>>();
    gate_k<<<BT, 256>>>(Dm, mnorm_w);
    run_gemm(p_y2, p_wt + OW_OUT, p_x2, BT, DM, DI, x, nullptr, 1);

    // ---- attention block ----
    rmsnorm_k<<<BT, 256>>>(p_x2, p_h, 1e-6f, 1);
    run_gemm(p_h, p_wt + OW_QKV, p_qkv, BT, QKVD, DM, nullptr, nullptr, 0);
    convqkv_k<<<BT, 256>>>(qconv_w, qconv_b, kconv_w, kconv_b, vconv_w, vconv_b);
    attn_k<<<BSZ * NHA * (TT / 64), 128, ATTN_SMEM>>>();
    run_gemm(p_att, p_wt + OW_CPROJ, p_x3, BT, DM, DM, p_x2, nullptr, 1);

    // ---- channel mix ----
    rmsnorm_k<<<BT, 256>>>(p_x3, p_h, 1e-6f, 0);
    shift_k<<<(BT * DM + 255) / 256, 256>>>(tmk, tmr);
    run_gemm(p_xk, p_wt + OW_KEY, p_kf, BT, FFND, DM, nullptr, nullptr, 2);
    run_gemm(p_kf, p_wt + OW_VAL, p_kv, BT, DM, FFND, nullptr, nullptr, 0);
    run_gemm(p_xr, p_wt + OW_REC, out, BT, DM, DM, p_x3, p_kv, 3);
}